// round 11
// baseline (speedup 1.0000x reference)
#include <cuda_runtime.h>
#include <cuda_bf16.h>
#include <math.h>

#define BB    4
#define CC    256
#define SL    2304     // 48*48
#define SG    144      // 12*12
#define HEADS 8
#define HD    32
#define SC    0.17677669529663687f

typedef unsigned long long u64;
typedef unsigned int u32;

// ---------------- f32x2 packed helpers ----------------
__device__ __forceinline__ u64 ffma2(u64 a, u64 b, u64 c) {
    u64 d;
    asm("fma.rn.f32x2 %0, %1, %2, %3;" : "=l"(d) : "l"(a), "l"(b), "l"(c));
    return d;
}
__device__ __forceinline__ u64 pack2(float x, float y) {
    u64 d;
    asm("mov.b64 %0, {%1, %2};" : "=l"(d) : "f"(x), "f"(y));
    return d;
}
__device__ __forceinline__ float2 unpack2(u64 v) {
    float2 r;
    asm("mov.b64 {%0, %1}, %2;" : "=f"(r.x), "=f"(r.y) : "l"(v));
    return r;
}
__device__ __forceinline__ void lds2(const float* p, u64& a, u64& b) {
    double2 t = *(const double2*)p;
    a = (u64)__double_as_longlong(t.x);
    b = (u64)__double_as_longlong(t.y);
}
__device__ __forceinline__ u32 pack_bf16x2(float lo, float hi) {
    u32 r;
    asm("cvt.rn.bf16x2.f32 %0, %1, %2;" : "=r"(r) : "f"(hi), "f"(lo));
    return r;
}
__device__ __forceinline__ u32 bf16_bits(float x) {
    u32 r;
    asm("cvt.rn.bf16x2.f32 %0, %1, %2;" : "=r"(r) : "f"(0.f), "f"(x));
    return r & 0xFFFFu;
}
__device__ __forceinline__ void split2(float x, float y, u32& hi, u32& lo) {
    u32 hx = bf16_bits(x), hy = bf16_bits(y);
    hi = hx | (hy << 16);
    float fx = __uint_as_float(hx << 16);
    float fy = __uint_as_float(hy << 16);
    lo = pack_bf16x2(x - fx, y - fy);
}
__device__ __forceinline__ void mma16816(float* c, const u32* a, const u32* b) {
    asm volatile("mma.sync.aligned.m16n8k16.row.col.f32.bf16.bf16.f32 "
        "{%0,%1,%2,%3}, {%4,%5,%6,%7}, {%8,%9}, {%0,%1,%2,%3};"
        : "+f"(c[0]), "+f"(c[1]), "+f"(c[2]), "+f"(c[3])
        : "r"(a[0]), "r"(a[1]), "r"(a[2]), "r"(a[3]), "r"(b[0]), "r"(b[1]));
}

// ---------------- scratch ----------------
__device__ float g_qkv   [BB*768*SL];
__device__ float g_qkvt  [BB*768*SL];
__device__ float g_attn  [BB*CC*SL];
__device__ float g_concat[(long)BB*512*SL];
__device__ float g_h     [BB*CC*SL];
__device__ float g_xc    [BB*CC*SG];
__device__ float g_qkvg  [BB*768*SG];
__device__ float g_qkvtg [BB*768*SG];
__device__ float g_attng [BB*CC*SG];
__device__ float g_g     [BB*CC*SG];
__device__ __nv_bfloat16 g_vt[BB*HEADS*32*SL];   // V^T bf16 [b,h,d,s]
__device__ float g_vsum[BB*HEADS*32];            // exact column sums of V
// W hi/lo splits (u32 = bf16x2 over c-pairs). Offsets (u32 units):
//   qkv_l: 0            (768*128  = 98304)
//   proj_l: 98304       (256*128  = 32768)
//   f1:    131072       (256*256  = 65536)
//   f2:    196608       (256*128  = 32768)   total 229376
#define WOFF_QKV  0
#define WOFF_PROJ 98304
#define WOFF_F1   131072
#define WOFF_F2   196608
__device__ u32 g_wh[229376];
__device__ u32 g_wl[229376];

// ---------------- weight split kernel ----------------
__global__ void wsplit_kernel(const float* __restrict__ W, u32* __restrict__ Wh,
                              u32* __restrict__ Wl, int n_pairs)
{
    int i = blockIdx.x * blockDim.x + threadIdx.x;
    if (i >= n_pairs) return;
    float x = W[2 * i], y = W[2 * i + 1];
    u32 h, l;
    split2(x, y, h, l);
    Wh[i] = h; Wl[i] = l;
}

// ---------------- TC conv1x1 GEMM: 3-pass bf16 split, pre-split W ----------------
// Tile 128o x 64s, 128 threads. FULL tiles only (Ssz % 64 == 0).
template<int GELU>
__global__ void __launch_bounds__(128)
gemm_tc_kernel(const float* __restrict__ X, const u32* __restrict__ Wh,
               const u32* __restrict__ Wl, const float* __restrict__ bias,
               float* __restrict__ Y, int Cin, int Ssz, long xBS, long yBS)
{
    __shared__ u32 sWh[128][12], sWl[128][12];  // [o][cpair] stride 12: conflict-free frags
    __shared__ u32 sXh[64][12],  sXl[64][12];   // [s][cpair]
    const int tid = threadIdx.x;
    const int w = tid >> 5, lane = tid & 31;
    const int g = lane >> 2, t = lane & 3;
    const int s0 = blockIdx.x * 64;
    const int o0 = blockIdx.y * 128;
    const int b  = blockIdx.z;
    const float* Xb = X + (long)b * xBS;
    const int cp = Cin >> 1;

    const int xcp = tid >> 4;       // cpair-base 0..7 (handles c rows 2*xcp, 2*xcp+1)
    const int xs  = (tid & 15) * 4; // s offset 0..60

    float acc[2][8][4];
    #pragma unroll
    for (int m = 0; m < 2; m++)
        #pragma unroll
        for (int n = 0; n < 8; n++)
            #pragma unroll
            for (int i = 0; i < 4; i++) acc[m][n][i] = 0.f;

    for (int c0 = 0; c0 < Cin; c0 += 16) {
        // stage W: thread tid -> o row tid; 8 u32 each from Wh/Wl (pre-split, no math)
        {
            const u32* whp = Wh + (long)(o0 + tid) * cp + (c0 >> 1);
            const u32* wlp = Wl + (long)(o0 + tid) * cp + (c0 >> 1);
            uint4 h0 = *(const uint4*)whp, h1 = *(const uint4*)(whp + 4);
            uint4 l0 = *(const uint4*)wlp, l1 = *(const uint4*)(wlp + 4);
            *(uint2*)&sWh[tid][0] = make_uint2(h0.x, h0.y);
            *(uint2*)&sWh[tid][2] = make_uint2(h0.z, h0.w);
            *(uint2*)&sWh[tid][4] = make_uint2(h1.x, h1.y);
            *(uint2*)&sWh[tid][6] = make_uint2(h1.z, h1.w);
            *(uint2*)&sWl[tid][0] = make_uint2(l0.x, l0.y);
            *(uint2*)&sWl[tid][2] = make_uint2(l0.z, l0.w);
            *(uint2*)&sWl[tid][4] = make_uint2(l1.x, l1.y);
            *(uint2*)&sWl[tid][6] = make_uint2(l1.z, l1.w);
        }
        // stage X chunk [16 c][64 s]: thread handles c rows (2*xcp, 2*xcp+1), 4 s values
        {
            const float* r0 = Xb + (long)(c0 + 2 * xcp) * Ssz + s0 + xs;
            const float* r1 = r0 + Ssz;
            float4 a = *(const float4*)r0;
            float4 c = *(const float4*)r1;
            u32 h, l;
            split2(a.x, c.x, h, l); sXh[xs][xcp] = h;     sXl[xs][xcp] = l;
            split2(a.y, c.y, h, l); sXh[xs + 1][xcp] = h; sXl[xs + 1][xcp] = l;
            split2(a.z, c.z, h, l); sXh[xs + 2][xcp] = h; sXl[xs + 2][xcp] = l;
            split2(a.w, c.w, h, l); sXh[xs + 3][xcp] = h; sXl[xs + 3][xcp] = l;
        }
        __syncthreads();

        u32 ah[2][4], al[2][4];
        #pragma unroll
        for (int m = 0; m < 2; m++) {
            int ro = w * 32 + m * 16;
            ah[m][0] = sWh[ro + g][t];         al[m][0] = sWl[ro + g][t];
            ah[m][1] = sWh[ro + g + 8][t];     al[m][1] = sWl[ro + g + 8][t];
            ah[m][2] = sWh[ro + g][t + 4];     al[m][2] = sWl[ro + g][t + 4];
            ah[m][3] = sWh[ro + g + 8][t + 4]; al[m][3] = sWl[ro + g + 8][t + 4];
        }
        #pragma unroll
        for (int n = 0; n < 8; n++) {
            u32 bh[2] = { sXh[n * 8 + g][t], sXh[n * 8 + g][t + 4] };
            u32 bl[2] = { sXl[n * 8 + g][t], sXl[n * 8 + g][t + 4] };
            mma16816(acc[0][n], ah[0], bh);
            mma16816(acc[1][n], ah[1], bh);
            mma16816(acc[0][n], al[0], bh);
            mma16816(acc[1][n], al[1], bh);
            mma16816(acc[0][n], ah[0], bl);
            mma16816(acc[1][n], ah[1], bl);
        }
        __syncthreads();
    }

    #pragma unroll
    for (int m = 0; m < 2; m++) {
        int o = o0 + w * 32 + m * 16 + g;
        float bv0 = bias ? bias[o] : 0.f;
        float bv1 = bias ? bias[o + 8] : 0.f;
        long base0 = (long)b * yBS + (long)o * Ssz;
        long base1 = base0 + 8L * Ssz;
        #pragma unroll
        for (int n = 0; n < 8; n++) {
            int s = s0 + n * 8 + 2 * t;
            float y00 = acc[m][n][0] + bv0, y01 = acc[m][n][1] + bv0;
            float y10 = acc[m][n][2] + bv1, y11 = acc[m][n][3] + bv1;
            if (GELU) {
                y00 = 0.5f * y00 * (1.f + erff(y00 * 0.70710678118654752f));
                y01 = 0.5f * y01 * (1.f + erff(y01 * 0.70710678118654752f));
                y10 = 0.5f * y10 * (1.f + erff(y10 * 0.70710678118654752f));
                y11 = 0.5f * y11 * (1.f + erff(y11 * 0.70710678118654752f));
            }
            *(float2*)&Y[base0 + s] = make_float2(y00, y01);
            *(float2*)&Y[base1 + s] = make_float2(y10, y11);
        }
    }
}

// ---------------- SIMT conv1x1 GEMM (global branch only) ----------------
template<int BM>
__global__ void __launch_bounds__(256)
gemm_kernel(const float* __restrict__ X, const float* __restrict__ Wm,
            const float* __restrict__ bias, float* __restrict__ Y,
            int Cin, int Ssz, long xBS, long yBS, int doGelu)
{
    constexpr int MR = BM / 16;
    constexpr int TPO = 16 / MR;
    __shared__ __align__(16) float Ws[16][BM];
    __shared__ __align__(16) float Xs[16][64];
    const int tx = threadIdx.x, ty = threadIdx.y;
    const int tid = ty * 16 + tx;
    const int s0 = blockIdx.x * 64;
    const int o0 = blockIdx.y * BM;
    const int b  = blockIdx.z;
    const float* Xb = X + (long)b * xBS;
    const bool full = (s0 + 64 <= Ssz);

    const int lw_o = tid / TPO;
    const int lw_c = (tid % TPO) * MR;
    const int lx_c = tid >> 4;
    const int lx_s = (tid & 15) * 4;

    u64 acc[MR][2];
    #pragma unroll
    for (int i = 0; i < MR; i++) { acc[i][0] = 0ULL; acc[i][1] = 0ULL; }

    for (int c0 = 0; c0 < Cin; c0 += 16) {
        {
            const float* wrow = Wm + (long)(o0 + lw_o) * Cin + c0 + lw_c;
            #pragma unroll
            for (int r = 0; r < MR; r += 4) {
                float4 w = *(const float4*)(wrow + r);
                Ws[lw_c + r + 0][lw_o] = w.x; Ws[lw_c + r + 1][lw_o] = w.y;
                Ws[lw_c + r + 2][lw_o] = w.z; Ws[lw_c + r + 3][lw_o] = w.w;
            }
        }
        {
            const float* xrow = Xb + (long)(c0 + lx_c) * Ssz + s0 + lx_s;
            if (full) {
                float4 xv = *(const float4*)xrow;
                Xs[lx_c][lx_s + 0] = xv.x; Xs[lx_c][lx_s + 1] = xv.y;
                Xs[lx_c][lx_s + 2] = xv.z; Xs[lx_c][lx_s + 3] = xv.w;
            } else {
                #pragma unroll
                for (int i = 0; i < 4; i++)
                    Xs[lx_c][lx_s + i] = (s0 + lx_s + i < Ssz) ? xrow[i] : 0.f;
            }
        }
        __syncthreads();

        #pragma unroll
        for (int c = 0; c < 16; c++) {
            u64 x01, x23;
            lds2(&Xs[c][tx * 4], x01, x23);
            #pragma unroll
            for (int r = 0; r < MR; r += 4) {
                float4 a = *(const float4*)&Ws[c][ty * MR + r];
                u64 p;
                p = pack2(a.x, a.x); acc[r+0][0] = ffma2(p, x01, acc[r+0][0]); acc[r+0][1] = ffma2(p, x23, acc[r+0][1]);
                p = pack2(a.y, a.y); acc[r+1][0] = ffma2(p, x01, acc[r+1][0]); acc[r+1][1] = ffma2(p, x23, acc[r+1][1]);
                p = pack2(a.z, a.z); acc[r+2][0] = ffma2(p, x01, acc[r+2][0]); acc[r+2][1] = ffma2(p, x23, acc[r+2][1]);
                p = pack2(a.w, a.w); acc[r+3][0] = ffma2(p, x01, acc[r+3][0]); acc[r+3][1] = ffma2(p, x23, acc[r+3][1]);
            }
        }
        __syncthreads();
    }

    #pragma unroll
    for (int i = 0; i < MR; i++) {
        int o = o0 + ty * MR + i;
        float bv = bias ? bias[o] : 0.f;
        float2 p0 = unpack2(acc[i][0]);
        float2 p1 = unpack2(acc[i][1]);
        float vals[4] = {p0.x, p0.y, p1.x, p1.y};
        #pragma unroll
        for (int j = 0; j < 4; j++) {
            int s = s0 + tx * 4 + j;
            if (s < Ssz) {
                float v = vals[j] + bv;
                if (doGelu) v = 0.5f * v * (1.f + erff(v * 0.70710678118654752f));
                Y[(long)b * yBS + (long)o * Ssz + s] = v;
            }
        }
    }
}

// ---------- transpose + L2-norm; for local V also emit bf16 V^T and exact colsums ----------
__global__ void tnorm_kernel(const float* __restrict__ qkv, float* __restrict__ qkvt, int Ssz,
                             __nv_bfloat16* __restrict__ vt, float* __restrict__ vsum, int doVt)
{
    __shared__ float sm[32][33];
    const int bp = blockIdx.y;
    const int b = bp / 24;
    const int rem = bp % 24;
    const int part = rem / 8;
    const int h = rem % 8;
    const int s0 = blockIdx.x * 32;
    const int tx = threadIdx.x, ty = threadIdx.y;

    {
        int s = s0 + tx;
        float v = 0.f;
        if (s < Ssz) v = qkv[((long)b * 768 + part * 256 + h * 32 + ty) * Ssz + s];
        sm[ty][tx] = v;
    }
    __syncthreads();

    if (doVt && part == 2) {
        float vo = sm[ty][tx];
        int s = s0 + tx;
        if (s < Ssz)
            vt[((long)(b * HEADS + h) * 32 + ty) * Ssz + s] = __float2bfloat16(vo);
        float sum = (s < Ssz) ? vo : 0.f;
        #pragma unroll
        for (int off = 16; off; off >>= 1) sum += __shfl_xor_sync(0xffffffffu, sum, off);
        if (tx == 0) atomicAdd(&vsum[(b * HEADS + h) * 32 + ty], sum);
    }

    float v = sm[tx][ty];
    if (part < 2) {
        float sq = v * v;
        #pragma unroll
        for (int off = 16; off; off >>= 1) sq += __shfl_xor_sync(0xffffffffu, sq, off);
        float n = sqrtf(sq);
        v = v / fmaxf(n, 1e-12f);
    }
    int s = s0 + ty;
    if (s < Ssz)
        qkvt[(((long)(b * 3 + part) * 8 + h) * Ssz + s) * 32 + tx] = v;
}

// ---------------- mma.sync bf16 flash attention (local branch) ----------------
__global__ void __launch_bounds__(128, 4)
attn_tc_kernel(const float* __restrict__ qkvt, const __nv_bfloat16* __restrict__ vt,
               const float* __restrict__ vsum, float* __restrict__ out)
{
    __shared__ u32 Ks[64][36];
    __shared__ u32 Vs[32][36];
    const int tid = threadIdx.x;
    const int w = tid >> 5, lane = tid & 31;
    const int g = lane >> 2, t = lane & 3;
    const int bh = blockIdx.x;
    const int b = bh >> 3, h = bh & 7;
    const int q0 = blockIdx.y * 128;
    const float* Q = qkvt + ((long)(b * 3) * HEADS + h) * (long)SL * HD;
    const float* K = Q + (long)HEADS * SL * HD;
    const char* Vg = (const char*)(vt + (long)bh * 32 * SL);

    u32 qa[2][2][4];
    #pragma unroll
    for (int m = 0; m < 2; m++) {
        int r0 = q0 + w * 32 + m * 16 + g;
        #pragma unroll
        for (int kt = 0; kt < 2; kt++) {
            int c = kt * 16 + 2 * t;
            const float* p0 = Q + (long)r0 * 32 + c;
            const float* p1 = Q + (long)(r0 + 8) * 32 + c;
            qa[m][kt][0] = pack_bf16x2(p0[0] * SC, p0[1] * SC);
            qa[m][kt][1] = pack_bf16x2(p1[0] * SC, p1[1] * SC);
            qa[m][kt][2] = pack_bf16x2(p0[8] * SC, p0[9] * SC);
            qa[m][kt][3] = pack_bf16x2(p1[8] * SC, p1[9] * SC);
        }
    }

    float oacc[2][4][4];
    #pragma unroll
    for (int m = 0; m < 2; m++)
        #pragma unroll
        for (int j = 0; j < 4; j++)
            #pragma unroll
            for (int i = 0; i < 4; i++) oacc[m][j][i] = 0.f;
    float lrow[2][2] = {{0.f, 0.f}, {0.f, 0.f}};

    for (int blk = 0; blk < 36; blk++) {
        const int k0 = blk * 64;
        {
            int r = tid >> 1, hf = tid & 1;
            const float* kr = K + (long)(k0 + r) * 32 + hf * 16;
            u32* kd = &Ks[r][hf * 8];
            #pragma unroll
            for (int i = 0; i < 8; i++) kd[i] = pack_bf16x2(kr[2 * i], kr[2 * i + 1]);
        }
        {
            int r = tid >> 2, s4 = tid & 3;
            const uint4* vr = (const uint4*)(Vg + (long)r * (SL * 2) + k0 * 2 + s4 * 32);
            uint4 v0 = vr[0], v1 = vr[1];
            u32* vd = &Vs[r][s4 * 8];
            vd[0] = v0.x; vd[1] = v0.y; vd[2] = v0.z; vd[3] = v0.w;
            vd[4] = v1.x; vd[5] = v1.y; vd[6] = v1.z; vd[7] = v1.w;
        }
        __syncthreads();

        #pragma unroll
        for (int hf = 0; hf < 2; hf++) {
            float sacc[2][4][4];
            #pragma unroll
            for (int m = 0; m < 2; m++)
                #pragma unroll
                for (int j = 0; j < 4; j++)
                    #pragma unroll
                    for (int i = 0; i < 4; i++) sacc[m][j][i] = 0.f;

            #pragma unroll
            for (int kt = 0; kt < 2; kt++)
                #pragma unroll
                for (int j = 0; j < 4; j++) {
                    int jj = hf * 4 + j;
                    u32 bb[2] = { Ks[8 * jj + g][kt * 8 + t], Ks[8 * jj + g][kt * 8 + t + 4] };
                    mma16816(sacc[0][j], qa[0][kt], bb);
                    mma16816(sacc[1][j], qa[1][kt], bb);
                }

            u32 fa[2][2][4];
            #pragma unroll
            for (int m = 0; m < 2; m++)
                #pragma unroll
                for (int j = 0; j < 4; j++) {
                    float p0 = __expf(sacc[m][j][0]);
                    float p1 = __expf(sacc[m][j][1]);
                    float p2 = __expf(sacc[m][j][2]);
                    float p3 = __expf(sacc[m][j][3]);
                    lrow[m][0] += p0 + p1;
                    lrow[m][1] += p2 + p3;
                    int kkl = j >> 1, hi2 = (j & 1) * 2;
                    fa[m][kkl][hi2 + 0] = pack_bf16x2(p0 - 1.f, p1 - 1.f);
                    fa[m][kkl][hi2 + 1] = pack_bf16x2(p2 - 1.f, p3 - 1.f);
                }

            #pragma unroll
            for (int kkl = 0; kkl < 2; kkl++) {
                int kk = hf * 2 + kkl;
                #pragma unroll
                for (int jn = 0; jn < 4; jn++) {
                    u32 bb[2] = { Vs[8 * jn + g][kk * 8 + t], Vs[8 * jn + g][kk * 8 + t + 4] };
                    mma16816(oacc[0][jn], fa[0][kkl], bb);
                    mma16816(oacc[1][jn], fa[1][kkl], bb);
                }
            }
        }
        __syncthreads();
    }

    #pragma unroll
    for (int m = 0; m < 2; m++)
        #pragma unroll
        for (int rh = 0; rh < 2; rh++) {
            float l = lrow[m][rh];
            l += __shfl_xor_sync(0xffffffffu, l, 1);
            l += __shfl_xor_sync(0xffffffffu, l, 2);
            lrow[m][rh] = l;
        }

    const float* vs = vsum + bh * 32;
    long ob = (long)b * CC + h * HD;
    #pragma unroll
    for (int m = 0; m < 2; m++)
        #pragma unroll
        for (int rh = 0; rh < 2; rh++) {
            float inv = 1.f / lrow[m][rh];
            int row = q0 + w * 32 + m * 16 + g + rh * 8;
            #pragma unroll
            for (int jn = 0; jn < 4; jn++) {
                int d = 8 * jn + 2 * t;
                float v0 = (__ldg(vs + d)     + oacc[m][jn][rh * 2 + 0]) * inv;
                float v1 = (__ldg(vs + d + 1) + oacc[m][jn][rh * 2 + 1]) * inv;
                out[(ob + d)     * (long)SL + row] = v0;
                out[(ob + d + 1) * (long)SL + row] = v1;
            }
        }
}

// ---------------- SIMT flash attention (global branch, S=144) ----------------
__global__ void __launch_bounds__(128, 2)
attn_kernel(const float* __restrict__ qkvt, float* __restrict__ out, int Ssz)
{
    __shared__ __align__(16) float ks[64][32];
    __shared__ __align__(16) float vs[64][32];
    const int bh = blockIdx.x;
    const int b = bh >> 3, h = bh & 7;
    const long base = ((long)(b * 3) * HEADS + h) * Ssz * HD;
    const float* Q = qkvt + base;
    const float* K = Q + (long)HEADS * Ssz * HD;
    const float* V = Q + 2L * HEADS * Ssz * HD;
    const int tid = threadIdx.x;
    const int rowa = blockIdx.y * 256 + tid;
    const int rowb = rowa + 128;
    const bool va = rowa < Ssz;
    const bool vb = rowb < Ssz;

    const u64 sc2 = pack2(SC, SC);

    u64 qa[16], qb[16];
    #pragma unroll
    for (int i = 0; i < 16; i++) { qa[i] = 0ULL; qb[i] = 0ULL; }
    if (va) {
        #pragma unroll
        for (int i = 0; i < 8; i++) {
            u64 t0, t1;
            lds2(Q + (long)rowa * 32 + i * 4, t0, t1);
            qa[2 * i] = ffma2(t0, sc2, 0ULL);
            qa[2 * i + 1] = ffma2(t1, sc2, 0ULL);
        }
    }
    if (vb) {
        #pragma unroll
        for (int i = 0; i < 8; i++) {
            u64 t0, t1;
            lds2(Q + (long)rowb * 32 + i * 4, t0, t1);
            qb[2 * i] = ffma2(t0, sc2, 0ULL);
            qb[2 * i + 1] = ffma2(t1, sc2, 0ULL);
        }
    }

    u64 aa[16], ab[16];
    #pragma unroll
    for (int i = 0; i < 16; i++) { aa[i] = 0ULL; ab[i] = 0ULL; }
    float la = 0.f, lb = 0.f;

    for (int j0 = 0; j0 < Ssz; j0 += 64) {
        int cnt = min(64, Ssz - j0);
        int nf4 = cnt * 8;
        const float4* kp = (const float4*)(K + (long)j0 * 32);
        const float4* vp = (const float4*)(V + (long)j0 * 32);
        #pragma unroll
        for (int t = 0; t < 4; t++) {
            int i = tid + t * 128;
            if (i < nf4) { ((float4*)ks)[i] = kp[i]; ((float4*)vs)[i] = vp[i]; }
        }
        __syncthreads();
        for (int j = 0; j < cnt; j++) {
            u64 kt[16];
            #pragma unroll
            for (int i = 0; i < 8; i++) lds2(&ks[j][i * 4], kt[2 * i], kt[2 * i + 1]);
            u64 da0 = 0ULL, da1 = 0ULL, db0 = 0ULL, db1 = 0ULL;
            #pragma unroll
            for (int i = 0; i < 16; i += 2) {
                da0 = ffma2(qa[i], kt[i], da0);
                da1 = ffma2(qa[i + 1], kt[i + 1], da1);
                db0 = ffma2(qb[i], kt[i], db0);
                db1 = ffma2(qb[i + 1], kt[i + 1], db1);
            }
            float2 ea0 = unpack2(da0), ea1 = unpack2(da1);
            float2 eb0 = unpack2(db0), eb1 = unpack2(db1);
            float pa = __expf((ea0.x + ea0.y) + (ea1.x + ea1.y));
            float pb = __expf((eb0.x + eb0.y) + (eb1.x + eb1.y));
            la += pa; lb += pb;
            u64 pa2 = pack2(pa, pa);
            u64 pb2 = pack2(pb, pb);
            u64 vt2[16];
            #pragma unroll
            for (int i = 0; i < 8; i++) lds2(&vs[j][i * 4], vt2[2 * i], vt2[2 * i + 1]);
            #pragma unroll
            for (int i = 0; i < 16; i++) {
                aa[i] = ffma2(pa2, vt2[i], aa[i]);
                ab[i] = ffma2(pb2, vt2[i], ab[i]);
            }
        }
        __syncthreads();
    }

    long ob = (long)b * CC + h * HD;
    if (va) {
        float inv = 1.f / la;
        #pragma unroll
        for (int i = 0; i < 16; i++) {
            float2 t = unpack2(aa[i]);
            out[(ob + 2 * i) * (long)Ssz + rowa] = t.x * inv;
            out[(ob + 2 * i + 1) * (long)Ssz + rowa] = t.y * inv;
        }
    }
    if (vb) {
        float inv = 1.f / lb;
        #pragma unroll
        for (int i = 0; i < 16; i++) {
            float2 t = unpack2(ab[i]);
            out[(ob + 2 * i) * (long)Ssz + rowb] = t.x * inv;
            out[(ob + 2 * i + 1) * (long)Ssz + rowb] = t.y * inv;
        }
    }
}

// ---------------- 4x4 average pool ----------------
__global__ void avgpool_kernel(const float* __restrict__ x, float* __restrict__ xc)
{
    int idx = blockIdx.x * blockDim.x + threadIdx.x;
    if (idx >= BB * CC * SG) return;
    int p = idx % SG;
    int c = (idx / SG) % CC;
    int b = idx / (SG * CC);
    int i = p / 12, j = p % 12;
    const float* xp = x + ((long)b * CC + c) * SL;
    float s = 0.f;
    #pragma unroll
    for (int dy = 0; dy < 4; dy++)
        #pragma unroll
        for (int dx = 0; dx < 4; dx++)
            s += xp[(i * 4 + dy) * 48 + j * 4 + dx];
    xc[idx] = s * (1.f / 16.f);
}

// ---------------- bilinear upsample into concat ch 256..511 ----------------
__global__ void upsample_kernel(const float* __restrict__ g, float* __restrict__ concat)
{
    int idx = blockIdx.x * blockDim.x + threadIdx.x;
    if (idx >= BB * CC * SL) return;
    int p = idx % SL;
    int c = (idx / SL) % CC;
    int b = idx / (SL * CC);
    int y = p / 48, x = p % 48;
    float fy = (y + 0.5f) * 0.25f - 0.5f;
    float fx = (x + 0.5f) * 0.25f - 0.5f;
    int y0 = (int)floorf(fy), x0 = (int)floorf(fx);
    float wy = fy - y0, wx = fx - x0;
    int ya = min(11, max(0, y0)), yb = min(11, max(0, y0 + 1));
    int xa = min(11, max(0, x0)), xb = min(11, max(0, x0 + 1));
    const float* gp = g + ((long)b * CC + c) * SG;
    float v00 = gp[ya * 12 + xa], v01 = gp[ya * 12 + xb];
    float v10 = gp[yb * 12 + xa], v11 = gp[yb * 12 + xb];
    float v = (1.f - wy) * ((1.f - wx) * v00 + wx * v01)
            +        wy  * ((1.f - wx) * v10 + wx * v11);
    concat[((long)b * 512 + 256 + c) * SL + p] = v;
}

// ---------------- launch ----------------
extern "C" void kernel_launch(void* const* d_in, const int* in_sizes, int n_in,
                              void* d_out, int out_size)
{
    const float* x        = (const float*)d_in[0];
    const float* w_qkv_l  = (const float*)d_in[1];
    const float* w_proj_l = (const float*)d_in[2];
    const float* b_proj_l = (const float*)d_in[3];
    const float* w_qkv_g  = (const float*)d_in[4];
    const float* w_proj_g = (const float*)d_in[5];
    const float* b_proj_g = (const float*)d_in[6];
    const float* w_f1     = (const float*)d_in[7];
    const float* b_f1     = (const float*)d_in[8];
    const float* w_f2     = (const float*)d_in[9];
    const float* b_f2     = (const float*)d_in[10];
    float* out = (float*)d_out;

    float *qkv, *qkvt, *attn, *concat, *hbuf, *xc, *qkvg, *qkvtg, *attng, *gg, *vsum;
    __nv_bfloat16* vt;
    u32 *wh, *wl;
    cudaGetSymbolAddress((void**)&qkv,    g_qkv);
    cudaGetSymbolAddress((void**)&qkvt,   g_qkvt);
    cudaGetSymbolAddress((void**)&attn,   g_attn);
    cudaGetSymbolAddress((void**)&concat, g_concat);
    cudaGetSymbolAddress((void**)&hbuf,   g_h);
    cudaGetSymbolAddress((void**)&xc,     g_xc);
    cudaGetSymbolAddress((void**)&qkvg,   g_qkvg);
    cudaGetSymbolAddress((void**)&qkvtg,  g_qkvtg);
    cudaGetSymbolAddress((void**)&attng,  g_attng);
    cudaGetSymbolAddress((void**)&gg,     g_g);
    cudaGetSymbolAddress((void**)&vt,     g_vt);
    cudaGetSymbolAddress((void**)&vsum,   g_vsum);
    cudaGetSymbolAddress((void**)&wh,     g_wh);
    cudaGetSymbolAddress((void**)&wl,     g_wl);

    dim3 blk(16, 16);

    cudaMemsetAsync(vsum, 0, BB * HEADS * 32 * sizeof(float));

    // weight splits (hi/lo bf16)
    wsplit_kernel<<<(98304 + 255) / 256, 256>>>(w_qkv_l,  wh + WOFF_QKV,  wl + WOFF_QKV,  98304);
    wsplit_kernel<<<(32768 + 255) / 256, 256>>>(w_proj_l, wh + WOFF_PROJ, wl + WOFF_PROJ, 32768);
    wsplit_kernel<<<(65536 + 255) / 256, 256>>>(w_f1,     wh + WOFF_F1,   wl + WOFF_F1,   65536);
    wsplit_kernel<<<(32768 + 255) / 256, 256>>>(w_f2,     wh + WOFF_F2,   wl + WOFF_F2,   32768);

    // local branch (TC GEMMs; SL % 64 == 0 so all tiles full)
    gemm_tc_kernel<0><<<dim3(SL / 64, 768 / 128, BB), 128>>>(x, wh + WOFF_QKV, wl + WOFF_QKV,
                                                             nullptr, qkv, 256, SL, 256L * SL, 768L * SL);
    tnorm_kernel<<<dim3(SL / 32, BB * 24), dim3(32, 32)>>>(qkv, qkvt, SL, vt, vsum, 1);
    attn_tc_kernel<<<dim3(BB * HEADS, SL / 128), 128>>>(qkvt, vt, vsum, attn);
    gemm_tc_kernel<0><<<dim3(SL / 64, 256 / 128, BB), 128>>>(attn, wh + WOFF_PROJ, wl + WOFF_PROJ,
                                                             b_proj_l, concat, 256, SL, 256L * SL, 512L * SL);

    // global branch (tiny; SIMT)
    avgpool_kernel<<<(BB * CC * SG + 255) / 256, 256>>>(x, xc);
    gemm_kernel<128><<<dim3((SG + 63) / 64, 768 / 128, BB), blk>>>(xc, w_qkv_g, nullptr, qkvg,
                                                                   256, SG, 256L * SG, 768L * SG, 0);
    tnorm_kernel<<<dim3((SG + 31) / 32, BB * 24), dim3(32, 32)>>>(qkvg, qkvtg, SG, vt, vsum, 0);
    attn_kernel<<<dim3(BB * HEADS, (SG + 255) / 256), 128>>>(qkvtg, attng, SG);
    gemm_kernel<128><<<dim3((SG + 63) / 64, 256 / 128, BB), blk>>>(attng, w_proj_g, b_proj_g, gg,
                                                                   256, SG, 256L * SG, 256L * SG, 0);
    upsample_kernel<<<(BB * CC * SL + 255) / 256, 256>>>(gg, concat);

    // fusion head (TC GEMMs)
    gemm_tc_kernel<1><<<dim3(SL / 64, 256 / 128, BB), 128>>>(concat, wh + WOFF_F1, wl + WOFF_F1,
                                                             b_f1, hbuf, 512, SL, 512L * SL, 256L * SL);
    gemm_tc_kernel<0><<<dim3(SL / 64, 256 / 128, BB), 128>>>(hbuf, wh + WOFF_F2, wl + WOFF_F2,
                                                             b_f2, out, 256, SL, 256L * SL, 256L * SL);
}

// round 12
// speedup vs baseline: 1.1660x; 1.1660x over previous
#include <cuda_runtime.h>
#include <cuda_bf16.h>
#include <math.h>

#define BB    4
#define CC    256
#define SL    2304     // 48*48
#define SG    144      // 12*12
#define HEADS 8
#define HD    32
#define SC    0.17677669529663687f

typedef unsigned long long u64;
typedef unsigned int u32;

// ---------------- f32x2 packed helpers ----------------
__device__ __forceinline__ u64 ffma2(u64 a, u64 b, u64 c) {
    u64 d;
    asm("fma.rn.f32x2 %0, %1, %2, %3;" : "=l"(d) : "l"(a), "l"(b), "l"(c));
    return d;
}
__device__ __forceinline__ u64 pack2(float x, float y) {
    u64 d;
    asm("mov.b64 %0, {%1, %2};" : "=l"(d) : "f"(x), "f"(y));
    return d;
}
__device__ __forceinline__ float2 unpack2(u64 v) {
    float2 r;
    asm("mov.b64 {%0, %1}, %2;" : "=f"(r.x), "=f"(r.y) : "l"(v));
    return r;
}
__device__ __forceinline__ void lds2(const float* p, u64& a, u64& b) {
    double2 t = *(const double2*)p;
    a = (u64)__double_as_longlong(t.x);
    b = (u64)__double_as_longlong(t.y);
}
__device__ __forceinline__ u32 pack_bf16x2(float lo, float hi) {
    u32 r;
    asm("cvt.rn.bf16x2.f32 %0, %1, %2;" : "=r"(r) : "f"(hi), "f"(lo));
    return r;
}
__device__ __forceinline__ u32 bf16_bits(float x) {
    u32 r;
    asm("cvt.rn.bf16x2.f32 %0, %1, %2;" : "=r"(r) : "f"(0.f), "f"(x));
    return r & 0xFFFFu;
}
__device__ __forceinline__ void split2(float x, float y, u32& hi, u32& lo) {
    u32 hx = bf16_bits(x), hy = bf16_bits(y);
    hi = hx | (hy << 16);
    float fx = __uint_as_float(hx << 16);
    float fy = __uint_as_float(hy << 16);
    lo = pack_bf16x2(x - fx, y - fy);
}
__device__ __forceinline__ void mma16816(float* c, const u32* a, const u32* b) {
    asm volatile("mma.sync.aligned.m16n8k16.row.col.f32.bf16.bf16.f32 "
        "{%0,%1,%2,%3}, {%4,%5,%6,%7}, {%8,%9}, {%0,%1,%2,%3};"
        : "+f"(c[0]), "+f"(c[1]), "+f"(c[2]), "+f"(c[3])
        : "r"(a[0]), "r"(a[1]), "r"(a[2]), "r"(a[3]), "r"(b[0]), "r"(b[1]));
}

// ---------------- scratch ----------------
__device__ float g_qkv   [BB*768*SL];
__device__ float g_qkvt  [BB*768*SL];
__device__ float g_attn  [BB*CC*SL];
__device__ float g_concat[(long)BB*512*SL];
__device__ float g_h     [BB*CC*SL];
__device__ float g_xc    [BB*CC*SG];
__device__ float g_qkvg  [BB*768*SG];
__device__ float g_qkvtg [BB*768*SG];
__device__ float g_attng [BB*CC*SG];
__device__ float g_g     [BB*CC*SG];
__device__ __nv_bfloat16 g_vt[BB*HEADS*32*SL];   // V^T bf16 [b,h,d,s]
__device__ u32 g_kb[BB*HEADS*SL*16];             // K bf16x2 d-pairs [b,h,s,16]
__device__ float g_vsum[BB*HEADS*32];            // exact column sums of V
// W hi/lo splits (u32 = bf16x2 over c-pairs)
#define WOFF_QKV  0
#define WOFF_PROJ 98304
#define WOFF_F1   131072
#define WOFF_F2   196608
#define WTOT      229376
__device__ u32 g_wh[WTOT];
__device__ u32 g_wl[WTOT];

// ---------------- combined weight split kernel (one launch) ----------------
__global__ void wsplit_all_kernel(const float* __restrict__ Wq, const float* __restrict__ Wp,
                                  const float* __restrict__ Wf1, const float* __restrict__ Wf2,
                                  u32* __restrict__ Wh, u32* __restrict__ Wl)
{
    int i = blockIdx.x * blockDim.x + threadIdx.x;
    if (i >= WTOT) return;
    const float* src;
    int off;
    if (i < WOFF_PROJ)      { src = Wq;  off = i - WOFF_QKV; }
    else if (i < WOFF_F1)   { src = Wp;  off = i - WOFF_PROJ; }
    else if (i < WOFF_F2)   { src = Wf1; off = i - WOFF_F1; }
    else                    { src = Wf2; off = i - WOFF_F2; }
    float x = src[2 * off], y = src[2 * off + 1];
    u32 h, l;
    split2(x, y, h, l);
    Wh[i] = h; Wl[i] = l;
}

// ---------------- TC conv1x1 GEMM: 3-pass bf16 split, pre-split W ----------------
// Tile 128o x 64s, 128 threads. FULL tiles only (Ssz % 64 == 0).
template<int GELU>
__global__ void __launch_bounds__(128)
gemm_tc_kernel(const float* __restrict__ X, const u32* __restrict__ Wh,
               const u32* __restrict__ Wl, const float* __restrict__ bias,
               float* __restrict__ Y, int Cin, int Ssz, long xBS, long yBS)
{
    __shared__ u32 sWh[128][12], sWl[128][12];
    __shared__ u32 sXh[64][12],  sXl[64][12];
    const int tid = threadIdx.x;
    const int w = tid >> 5, lane = tid & 31;
    const int g = lane >> 2, t = lane & 3;
    const int s0 = blockIdx.x * 64;
    const int o0 = blockIdx.y * 128;
    const int b  = blockIdx.z;
    const float* Xb = X + (long)b * xBS;
    const int cp = Cin >> 1;

    const int xcp = tid >> 4;
    const int xs  = (tid & 15) * 4;

    float acc[2][8][4];
    #pragma unroll
    for (int m = 0; m < 2; m++)
        #pragma unroll
        for (int n = 0; n < 8; n++)
            #pragma unroll
            for (int i = 0; i < 4; i++) acc[m][n][i] = 0.f;

    for (int c0 = 0; c0 < Cin; c0 += 16) {
        {
            const u32* whp = Wh + (long)(o0 + tid) * cp + (c0 >> 1);
            const u32* wlp = Wl + (long)(o0 + tid) * cp + (c0 >> 1);
            uint4 h0 = *(const uint4*)whp, h1 = *(const uint4*)(whp + 4);
            uint4 l0 = *(const uint4*)wlp, l1 = *(const uint4*)(wlp + 4);
            *(uint2*)&sWh[tid][0] = make_uint2(h0.x, h0.y);
            *(uint2*)&sWh[tid][2] = make_uint2(h0.z, h0.w);
            *(uint2*)&sWh[tid][4] = make_uint2(h1.x, h1.y);
            *(uint2*)&sWh[tid][6] = make_uint2(h1.z, h1.w);
            *(uint2*)&sWl[tid][0] = make_uint2(l0.x, l0.y);
            *(uint2*)&sWl[tid][2] = make_uint2(l0.z, l0.w);
            *(uint2*)&sWl[tid][4] = make_uint2(l1.x, l1.y);
            *(uint2*)&sWl[tid][6] = make_uint2(l1.z, l1.w);
        }
        {
            const float* r0 = Xb + (long)(c0 + 2 * xcp) * Ssz + s0 + xs;
            const float* r1 = r0 + Ssz;
            float4 a = *(const float4*)r0;
            float4 c = *(const float4*)r1;
            u32 h, l;
            split2(a.x, c.x, h, l); sXh[xs][xcp] = h;     sXl[xs][xcp] = l;
            split2(a.y, c.y, h, l); sXh[xs + 1][xcp] = h; sXl[xs + 1][xcp] = l;
            split2(a.z, c.z, h, l); sXh[xs + 2][xcp] = h; sXl[xs + 2][xcp] = l;
            split2(a.w, c.w, h, l); sXh[xs + 3][xcp] = h; sXl[xs + 3][xcp] = l;
        }
        __syncthreads();

        u32 ah[2][4], al[2][4];
        #pragma unroll
        for (int m = 0; m < 2; m++) {
            int ro = w * 32 + m * 16;
            ah[m][0] = sWh[ro + g][t];         al[m][0] = sWl[ro + g][t];
            ah[m][1] = sWh[ro + g + 8][t];     al[m][1] = sWl[ro + g + 8][t];
            ah[m][2] = sWh[ro + g][t + 4];     al[m][2] = sWl[ro + g][t + 4];
            ah[m][3] = sWh[ro + g + 8][t + 4]; al[m][3] = sWl[ro + g + 8][t + 4];
        }
        #pragma unroll
        for (int n = 0; n < 8; n++) {
            u32 bh[2] = { sXh[n * 8 + g][t], sXh[n * 8 + g][t + 4] };
            u32 bl[2] = { sXl[n * 8 + g][t], sXl[n * 8 + g][t + 4] };
            mma16816(acc[0][n], ah[0], bh);
            mma16816(acc[1][n], ah[1], bh);
            mma16816(acc[0][n], al[0], bh);
            mma16816(acc[1][n], al[1], bh);
            mma16816(acc[0][n], ah[0], bl);
            mma16816(acc[1][n], ah[1], bl);
        }
        __syncthreads();
    }

    #pragma unroll
    for (int m = 0; m < 2; m++) {
        int o = o0 + w * 32 + m * 16 + g;
        float bv0 = bias ? bias[o] : 0.f;
        float bv1 = bias ? bias[o + 8] : 0.f;
        long base0 = (long)b * yBS + (long)o * Ssz;
        long base1 = base0 + 8L * Ssz;
        #pragma unroll
        for (int n = 0; n < 8; n++) {
            int s = s0 + n * 8 + 2 * t;
            float y00 = acc[m][n][0] + bv0, y01 = acc[m][n][1] + bv0;
            float y10 = acc[m][n][2] + bv1, y11 = acc[m][n][3] + bv1;
            if (GELU) {
                y00 = 0.5f * y00 * (1.f + erff(y00 * 0.70710678118654752f));
                y01 = 0.5f * y01 * (1.f + erff(y01 * 0.70710678118654752f));
                y10 = 0.5f * y10 * (1.f + erff(y10 * 0.70710678118654752f));
                y11 = 0.5f * y11 * (1.f + erff(y11 * 0.70710678118654752f));
            }
            *(float2*)&Y[base0 + s] = make_float2(y00, y01);
            *(float2*)&Y[base1 + s] = make_float2(y10, y11);
        }
    }
}

// ---------------- SIMT conv1x1 GEMM (global branch only) ----------------
template<int BM>
__global__ void __launch_bounds__(256)
gemm_kernel(const float* __restrict__ X, const float* __restrict__ Wm,
            const float* __restrict__ bias, float* __restrict__ Y,
            int Cin, int Ssz, long xBS, long yBS, int doGelu)
{
    constexpr int MR = BM / 16;
    constexpr int TPO = 16 / MR;
    __shared__ __align__(16) float Ws[16][BM];
    __shared__ __align__(16) float Xs[16][64];
    const int tx = threadIdx.x, ty = threadIdx.y;
    const int tid = ty * 16 + tx;
    const int s0 = blockIdx.x * 64;
    const int o0 = blockIdx.y * BM;
    const int b  = blockIdx.z;
    const float* Xb = X + (long)b * xBS;
    const bool full = (s0 + 64 <= Ssz);

    const int lw_o = tid / TPO;
    const int lw_c = (tid % TPO) * MR;
    const int lx_c = tid >> 4;
    const int lx_s = (tid & 15) * 4;

    u64 acc[MR][2];
    #pragma unroll
    for (int i = 0; i < MR; i++) { acc[i][0] = 0ULL; acc[i][1] = 0ULL; }

    for (int c0 = 0; c0 < Cin; c0 += 16) {
        {
            const float* wrow = Wm + (long)(o0 + lw_o) * Cin + c0 + lw_c;
            #pragma unroll
            for (int r = 0; r < MR; r += 4) {
                float4 w = *(const float4*)(wrow + r);
                Ws[lw_c + r + 0][lw_o] = w.x; Ws[lw_c + r + 1][lw_o] = w.y;
                Ws[lw_c + r + 2][lw_o] = w.z; Ws[lw_c + r + 3][lw_o] = w.w;
            }
        }
        {
            const float* xrow = Xb + (long)(c0 + lx_c) * Ssz + s0 + lx_s;
            if (full) {
                float4 xv = *(const float4*)xrow;
                Xs[lx_c][lx_s + 0] = xv.x; Xs[lx_c][lx_s + 1] = xv.y;
                Xs[lx_c][lx_s + 2] = xv.z; Xs[lx_c][lx_s + 3] = xv.w;
            } else {
                #pragma unroll
                for (int i = 0; i < 4; i++)
                    Xs[lx_c][lx_s + i] = (s0 + lx_s + i < Ssz) ? xrow[i] : 0.f;
            }
        }
        __syncthreads();

        #pragma unroll
        for (int c = 0; c < 16; c++) {
            u64 x01, x23;
            lds2(&Xs[c][tx * 4], x01, x23);
            #pragma unroll
            for (int r = 0; r < MR; r += 4) {
                float4 a = *(const float4*)&Ws[c][ty * MR + r];
                u64 p;
                p = pack2(a.x, a.x); acc[r+0][0] = ffma2(p, x01, acc[r+0][0]); acc[r+0][1] = ffma2(p, x23, acc[r+0][1]);
                p = pack2(a.y, a.y); acc[r+1][0] = ffma2(p, x01, acc[r+1][0]); acc[r+1][1] = ffma2(p, x23, acc[r+1][1]);
                p = pack2(a.z, a.z); acc[r+2][0] = ffma2(p, x01, acc[r+2][0]); acc[r+2][1] = ffma2(p, x23, acc[r+2][1]);
                p = pack2(a.w, a.w); acc[r+3][0] = ffma2(p, x01, acc[r+3][0]); acc[r+3][1] = ffma2(p, x23, acc[r+3][1]);
            }
        }
        __syncthreads();
    }

    #pragma unroll
    for (int i = 0; i < MR; i++) {
        int o = o0 + ty * MR + i;
        float bv = bias ? bias[o] : 0.f;
        float2 p0 = unpack2(acc[i][0]);
        float2 p1 = unpack2(acc[i][1]);
        float vals[4] = {p0.x, p0.y, p1.x, p1.y};
        #pragma unroll
        for (int j = 0; j < 4; j++) {
            int s = s0 + tx * 4 + j;
            if (s < Ssz) {
                float v = vals[j] + bv;
                if (doGelu) v = 0.5f * v * (1.f + erff(v * 0.70710678118654752f));
                Y[(long)b * yBS + (long)o * Ssz + s] = v;
            }
        }
    }
}

// ---- transpose + L2-norm; local: also emit bf16 V^T + vsum + bf16 K d-pairs ----
__global__ void tnorm_kernel(const float* __restrict__ qkv, float* __restrict__ qkvt, int Ssz,
                             __nv_bfloat16* __restrict__ vt, float* __restrict__ vsum,
                             u32* __restrict__ kb, int doAux)
{
    __shared__ float sm[32][33];
    const int bp = blockIdx.y;
    const int b = bp / 24;
    const int rem = bp % 24;
    const int part = rem / 8;
    const int h = rem % 8;
    const int s0 = blockIdx.x * 32;
    const int tx = threadIdx.x, ty = threadIdx.y;

    {
        int s = s0 + tx;
        float v = 0.f;
        if (s < Ssz) v = qkv[((long)b * 768 + part * 256 + h * 32 + ty) * Ssz + s];
        sm[ty][tx] = v;
    }
    __syncthreads();

    if (doAux && part == 2) {
        float vo = sm[ty][tx];
        int s = s0 + tx;
        if (s < Ssz)
            vt[((long)(b * HEADS + h) * 32 + ty) * Ssz + s] = __float2bfloat16(vo);
        float sum = (s < Ssz) ? vo : 0.f;
        #pragma unroll
        for (int off = 16; off; off >>= 1) sum += __shfl_xor_sync(0xffffffffu, sum, off);
        if (tx == 0) atomicAdd(&vsum[(b * HEADS + h) * 32 + ty], sum);
    }

    float v = sm[tx][ty];   // value at (d = tx, s = s0 + ty)
    if (part < 2) {
        float sq = v * v;
        #pragma unroll
        for (int off = 16; off; off >>= 1) sq += __shfl_xor_sync(0xffffffffu, sq, off);
        float n = sqrtf(sq);
        v = v / fmaxf(n, 1e-12f);
    }
    int s = s0 + ty;
    if (s < Ssz)
        qkvt[(((long)(b * 3 + part) * 8 + h) * Ssz + s) * 32 + tx] = v;

    // K bf16 d-pairs for the TC attention (local branch): kb[((bh*SL + s)*16 + d/2]
    if (doAux && part == 1 && s < Ssz) {
        float vhi = __shfl_down_sync(0xffffffffu, v, 1);
        if ((tx & 1) == 0)
            kb[((long)(b * HEADS + h) * SL + s) * 16 + (tx >> 1)] = pack_bf16x2(v, vhi);
    }
}

// ---------------- mma.sync bf16 flash attention (local branch) ----------------
__global__ void __launch_bounds__(128, 4)
attn_tc_kernel(const float* __restrict__ qkvt, const u32* __restrict__ kb,
               const __nv_bfloat16* __restrict__ vt,
               const float* __restrict__ vsum, float* __restrict__ out)
{
    __shared__ u32 Ks[64][36];
    __shared__ u32 Vs[32][36];
    const int tid = threadIdx.x;
    const int w = tid >> 5, lane = tid & 31;
    const int g = lane >> 2, t = lane & 3;
    const int bh = blockIdx.x;
    const int b = bh >> 3, h = bh & 7;
    const int q0 = blockIdx.y * 128;
    const float* Q = qkvt + ((long)(b * 3) * HEADS + h) * (long)SL * HD;
    const u32* Kb = kb + (long)bh * SL * 16;
    const char* Vg = (const char*)(vt + (long)bh * 32 * SL);

    u32 qa[2][2][4];
    #pragma unroll
    for (int m = 0; m < 2; m++) {
        int r0 = q0 + w * 32 + m * 16 + g;
        #pragma unroll
        for (int kt = 0; kt < 2; kt++) {
            int c = kt * 16 + 2 * t;
            const float* p0 = Q + (long)r0 * 32 + c;
            const float* p1 = Q + (long)(r0 + 8) * 32 + c;
            qa[m][kt][0] = pack_bf16x2(p0[0] * SC, p0[1] * SC);
            qa[m][kt][1] = pack_bf16x2(p1[0] * SC, p1[1] * SC);
            qa[m][kt][2] = pack_bf16x2(p0[8] * SC, p0[9] * SC);
            qa[m][kt][3] = pack_bf16x2(p1[8] * SC, p1[9] * SC);
        }
    }

    float oacc[2][4][4];
    #pragma unroll
    for (int m = 0; m < 2; m++)
        #pragma unroll
        for (int j = 0; j < 4; j++)
            #pragma unroll
            for (int i = 0; i < 4; i++) oacc[m][j][i] = 0.f;
    float lrow[2][2] = {{0.f, 0.f}, {0.f, 0.f}};

    for (int blk = 0; blk < 36; blk++) {
        const int k0 = blk * 64;
        // stage K: pure u32 copy of precomputed bf16 d-pairs
        {
            int r = tid >> 1, hf = (tid & 1) * 8;
            const uint4* kp = (const uint4*)(Kb + ((long)(k0 + r) * 16 + hf));
            uint4 k0v = kp[0], k1v = kp[1];
            u32* kd = &Ks[r][hf];
            kd[0] = k0v.x; kd[1] = k0v.y; kd[2] = k0v.z; kd[3] = k0v.w;
            kd[4] = k1v.x; kd[5] = k1v.y; kd[6] = k1v.z; kd[7] = k1v.w;
        }
        {
            int r = tid >> 2, s4 = tid & 3;
            const uint4* vr = (const uint4*)(Vg + (long)r * (SL * 2) + k0 * 2 + s4 * 32);
            uint4 v0 = vr[0], v1 = vr[1];
            u32* vd = &Vs[r][s4 * 8];
            vd[0] = v0.x; vd[1] = v0.y; vd[2] = v0.z; vd[3] = v0.w;
            vd[4] = v1.x; vd[5] = v1.y; vd[6] = v1.z; vd[7] = v1.w;
        }
        __syncthreads();

        #pragma unroll
        for (int hf = 0; hf < 2; hf++) {
            float sacc[2][4][4];
            #pragma unroll
            for (int m = 0; m < 2; m++)
                #pragma unroll
                for (int j = 0; j < 4; j++)
                    #pragma unroll
                    for (int i = 0; i < 4; i++) sacc[m][j][i] = 0.f;

            #pragma unroll
            for (int kt = 0; kt < 2; kt++)
                #pragma unroll
                for (int j = 0; j < 4; j++) {
                    int jj = hf * 4 + j;
                    u32 bb[2] = { Ks[8 * jj + g][kt * 8 + t], Ks[8 * jj + g][kt * 8 + t + 4] };
                    mma16816(sacc[0][j], qa[0][kt], bb);
                    mma16816(sacc[1][j], qa[1][kt], bb);
                }

            u32 fa[2][2][4];
            #pragma unroll
            for (int m = 0; m < 2; m++)
                #pragma unroll
                for (int j = 0; j < 4; j++) {
                    float p0 = __expf(sacc[m][j][0]);
                    float p1 = __expf(sacc[m][j][1]);
                    float p2 = __expf(sacc[m][j][2]);
                    float p3 = __expf(sacc[m][j][3]);
                    lrow[m][0] += p0 + p1;
                    lrow[m][1] += p2 + p3;
                    int kkl = j >> 1, hi2 = (j & 1) * 2;
                    fa[m][kkl][hi2 + 0] = pack_bf16x2(p0 - 1.f, p1 - 1.f);
                    fa[m][kkl][hi2 + 1] = pack_bf16x2(p2 - 1.f, p3 - 1.f);
                }

            #pragma unroll
            for (int kkl = 0; kkl < 2; kkl++) {
                int kk = hf * 2 + kkl;
                #pragma unroll
                for (int jn = 0; jn < 4; jn++) {
                    u32 bb[2] = { Vs[8 * jn + g][kk * 8 + t], Vs[8 * jn + g][kk * 8 + t + 4] };
                    mma16816(oacc[0][jn], fa[0][kkl], bb);
                    mma16816(oacc[1][jn], fa[1][kkl], bb);
                }
            }
        }
        __syncthreads();
    }

    #pragma unroll
    for (int m = 0; m < 2; m++)
        #pragma unroll
        for (int rh = 0; rh < 2; rh++) {
            float l = lrow[m][rh];
            l += __shfl_xor_sync(0xffffffffu, l, 1);
            l += __shfl_xor_sync(0xffffffffu, l, 2);
            lrow[m][rh] = l;
        }

    const float* vs = vsum + bh * 32;
    long ob = (long)b * CC + h * HD;
    #pragma unroll
    for (int m = 0; m < 2; m++)
        #pragma unroll
        for (int rh = 0; rh < 2; rh++) {
            float inv = 1.f / lrow[m][rh];
            int row = q0 + w * 32 + m * 16 + g + rh * 8;
            #pragma unroll
            for (int jn = 0; jn < 4; jn++) {
                int d = 8 * jn + 2 * t;
                float v0 = (__ldg(vs + d)     + oacc[m][jn][rh * 2 + 0]) * inv;
                float v1 = (__ldg(vs + d + 1) + oacc[m][jn][rh * 2 + 1]) * inv;
                out[(ob + d)     * (long)SL + row] = v0;
                out[(ob + d + 1) * (long)SL + row] = v1;
            }
        }
}

// ---------------- SIMT flash attention (global branch, S=144) ----------------
__global__ void __launch_bounds__(128, 2)
attn_kernel(const float* __restrict__ qkvt, float* __restrict__ out, int Ssz)
{
    __shared__ __align__(16) float ks[64][32];
    __shared__ __align__(16) float vs[64][32];
    const int bh = blockIdx.x;
    const int b = bh >> 3, h = bh & 7;
    const long base = ((long)(b * 3) * HEADS + h) * Ssz * HD;
    const float* Q = qkvt + base;
    const float* K = Q + (long)HEADS * Ssz * HD;
    const float* V = Q + 2L * HEADS * Ssz * HD;
    const int tid = threadIdx.x;
    const int rowa = blockIdx.y * 256 + tid;
    const int rowb = rowa + 128;
    const bool va = rowa < Ssz;
    const bool vb = rowb < Ssz;

    const u64 sc2 = pack2(SC, SC);

    u64 qa[16], qb[16];
    #pragma unroll
    for (int i = 0; i < 16; i++) { qa[i] = 0ULL; qb[i] = 0ULL; }
    if (va) {
        #pragma unroll
        for (int i = 0; i < 8; i++) {
            u64 t0, t1;
            lds2(Q + (long)rowa * 32 + i * 4, t0, t1);
            qa[2 * i] = ffma2(t0, sc2, 0ULL);
            qa[2 * i + 1] = ffma2(t1, sc2, 0ULL);
        }
    }
    if (vb) {
        #pragma unroll
        for (int i = 0; i < 8; i++) {
            u64 t0, t1;
            lds2(Q + (long)rowb * 32 + i * 4, t0, t1);
            qb[2 * i] = ffma2(t0, sc2, 0ULL);
            qb[2 * i + 1] = ffma2(t1, sc2, 0ULL);
        }
    }

    u64 aa[16], ab[16];
    #pragma unroll
    for (int i = 0; i < 16; i++) { aa[i] = 0ULL; ab[i] = 0ULL; }
    float la = 0.f, lb = 0.f;

    for (int j0 = 0; j0 < Ssz; j0 += 64) {
        int cnt = min(64, Ssz - j0);
        int nf4 = cnt * 8;
        const float4* kp = (const float4*)(K + (long)j0 * 32);
        const float4* vp = (const float4*)(V + (long)j0 * 32);
        #pragma unroll
        for (int t = 0; t < 4; t++) {
            int i = tid + t * 128;
            if (i < nf4) { ((float4*)ks)[i] = kp[i]; ((float4*)vs)[i] = vp[i]; }
        }
        __syncthreads();
        for (int j = 0; j < cnt; j++) {
            u64 kt[16];
            #pragma unroll
            for (int i = 0; i < 8; i++) lds2(&ks[j][i * 4], kt[2 * i], kt[2 * i + 1]);
            u64 da0 = 0ULL, da1 = 0ULL, db0 = 0ULL, db1 = 0ULL;
            #pragma unroll
            for (int i = 0; i < 16; i += 2) {
                da0 = ffma2(qa[i], kt[i], da0);
                da1 = ffma2(qa[i + 1], kt[i + 1], da1);
                db0 = ffma2(qb[i], kt[i], db0);
                db1 = ffma2(qb[i + 1], kt[i + 1], db1);
            }
            float2 ea0 = unpack2(da0), ea1 = unpack2(da1);
            float2 eb0 = unpack2(db0), eb1 = unpack2(db1);
            float pa = __expf((ea0.x + ea0.y) + (ea1.x + ea1.y));
            float pb = __expf((eb0.x + eb0.y) + (eb1.x + eb1.y));
            la += pa; lb += pb;
            u64 pa2 = pack2(pa, pa);
            u64 pb2 = pack2(pb, pb);
            u64 vt2[16];
            #pragma unroll
            for (int i = 0; i < 8; i++) lds2(&vs[j][i * 4], vt2[2 * i], vt2[2 * i + 1]);
            #pragma unroll
            for (int i = 0; i < 16; i++) {
                aa[i] = ffma2(pa2, vt2[i], aa[i]);
                ab[i] = ffma2(pb2, vt2[i], ab[i]);
            }
        }
        __syncthreads();
    }

    long ob = (long)b * CC + h * HD;
    if (va) {
        float inv = 1.f / la;
        #pragma unroll
        for (int i = 0; i < 16; i++) {
            float2 t = unpack2(aa[i]);
            out[(ob + 2 * i) * (long)Ssz + rowa] = t.x * inv;
            out[(ob + 2 * i + 1) * (long)Ssz + rowa] = t.y * inv;
        }
    }
    if (vb) {
        float inv = 1.f / lb;
        #pragma unroll
        for (int i = 0; i < 16; i++) {
            float2 t = unpack2(ab[i]);
            out[(ob + 2 * i) * (long)Ssz + rowb] = t.x * inv;
            out[(ob + 2 * i + 1) * (long)Ssz + rowb] = t.y * inv;
        }
    }
}

// ---------------- 4x4 average pool ----------------
__global__ void avgpool_kernel(const float* __restrict__ x, float* __restrict__ xc)
{
    int idx = blockIdx.x * blockDim.x + threadIdx.x;
    if (idx >= BB * CC * SG) return;
    int p = idx % SG;
    int c = (idx / SG) % CC;
    int b = idx / (SG * CC);
    int i = p / 12, j = p % 12;
    const float* xp = x + ((long)b * CC + c) * SL;
    float s = 0.f;
    #pragma unroll
    for (int dy = 0; dy < 4; dy++)
        #pragma unroll
        for (int dx = 0; dx < 4; dx++)
            s += xp[(i * 4 + dy) * 48 + j * 4 + dx];
    xc[idx] = s * (1.f / 16.f);
}

// ---------------- bilinear upsample into concat ch 256..511 ----------------
__global__ void upsample_kernel(const float* __restrict__ g, float* __restrict__ concat)
{
    int idx = blockIdx.x * blockDim.x + threadIdx.x;
    if (idx >= BB * CC * SL) return;
    int p = idx % SL;
    int c = (idx / SL) % CC;
    int b = idx / (SL * CC);
    int y = p / 48, x = p % 48;
    float fy = (y + 0.5f) * 0.25f - 0.5f;
    float fx = (x + 0.5f) * 0.25f - 0.5f;
    int y0 = (int)floorf(fy), x0 = (int)floorf(fx);
    float wy = fy - y0, wx = fx - x0;
    int ya = min(11, max(0, y0)), yb = min(11, max(0, y0 + 1));
    int xa = min(11, max(0, x0)), xb = min(11, max(0, x0 + 1));
    const float* gp = g + ((long)b * CC + c) * SG;
    float v00 = gp[ya * 12 + xa], v01 = gp[ya * 12 + xb];
    float v10 = gp[yb * 12 + xa], v11 = gp[yb * 12 + xb];
    float v = (1.f - wy) * ((1.f - wx) * v00 + wx * v01)
            +        wy  * ((1.f - wx) * v10 + wx * v11);
    concat[((long)b * 512 + 256 + c) * SL + p] = v;
}

// ---------------- launch ----------------
extern "C" void kernel_launch(void* const* d_in, const int* in_sizes, int n_in,
                              void* d_out, int out_size)
{
    const float* x        = (const float*)d_in[0];
    const float* w_qkv_l  = (const float*)d_in[1];
    const float* w_proj_l = (const float*)d_in[2];
    const float* b_proj_l = (const float*)d_in[3];
    const float* w_qkv_g  = (const float*)d_in[4];
    const float* w_proj_g = (const float*)d_in[5];
    const float* b_proj_g = (const float*)d_in[6];
    const float* w_f1     = (const float*)d_in[7];
    const float* b_f1     = (const float*)d_in[8];
    const float* w_f2     = (const float*)d_in[9];
    const float* b_f2     = (const float*)d_in[10];
    float* out = (float*)d_out;

    float *qkv, *qkvt, *attn, *concat, *hbuf, *xc, *qkvg, *qkvtg, *attng, *gg, *vsum;
    __nv_bfloat16* vt;
    u32 *wh, *wl, *kb;
    cudaGetSymbolAddress((void**)&qkv,    g_qkv);
    cudaGetSymbolAddress((void**)&qkvt,   g_qkvt);
    cudaGetSymbolAddress((void**)&attn,   g_attn);
    cudaGetSymbolAddress((void**)&concat, g_concat);
    cudaGetSymbolAddress((void**)&hbuf,   g_h);
    cudaGetSymbolAddress((void**)&xc,     g_xc);
    cudaGetSymbolAddress((void**)&qkvg,   g_qkvg);
    cudaGetSymbolAddress((void**)&qkvtg,  g_qkvtg);
    cudaGetSymbolAddress((void**)&attng,  g_attng);
    cudaGetSymbolAddress((void**)&gg,     g_g);
    cudaGetSymbolAddress((void**)&vt,     g_vt);
    cudaGetSymbolAddress((void**)&vsum,   g_vsum);
    cudaGetSymbolAddress((void**)&wh,     g_wh);
    cudaGetSymbolAddress((void**)&wl,     g_wl);
    cudaGetSymbolAddress((void**)&kb,     g_kb);

    dim3 blk(16, 16);

    cudaMemsetAsync(vsum, 0, BB * HEADS * 32 * sizeof(float));

    // all weight splits in ONE launch
    wsplit_all_kernel<<<(WTOT + 255) / 256, 256>>>(w_qkv_l, w_proj_l, w_f1, w_f2, wh, wl);

    // local branch (TC GEMMs; SL % 64 == 0 so all tiles full)
    gemm_tc_kernel<0><<<dim3(SL / 64, 768 / 128, BB), 128>>>(x, wh + WOFF_QKV, wl + WOFF_QKV,
                                                             nullptr, qkv, 256, SL, 256L * SL, 768L * SL);
    tnorm_kernel<<<dim3(SL / 32, BB * 24), dim3(32, 32)>>>(qkv, qkvt, SL, vt, vsum, kb, 1);
    attn_tc_kernel<<<dim3(BB * HEADS, SL / 128), 128>>>(qkvt, kb, vt, vsum, attn);
    gemm_tc_kernel<0><<<dim3(SL / 64, 256 / 128, BB), 128>>>(attn, wh + WOFF_PROJ, wl + WOFF_PROJ,
                                                             b_proj_l, concat, 256, SL, 256L * SL, 512L * SL);

    // global branch (tiny; SIMT)
    avgpool_kernel<<<(BB * CC * SG + 255) / 256, 256>>>(x, xc);
    gemm_kernel<128><<<dim3((SG + 63) / 64, 768 / 128, BB), blk>>>(xc, w_qkv_g, nullptr, qkvg,
                                                                   256, SG, 256L * SG, 768L * SG, 0);
    tnorm_kernel<<<dim3((SG + 31) / 32, BB * 24), dim3(32, 32)>>>(qkvg, qkvtg, SG, vt, vsum, kb, 0);
    attn_kernel<<<dim3(BB * HEADS, (SG + 255) / 256), 128>>>(qkvtg, attng, SG);
    gemm_kernel<128><<<dim3((SG + 63) / 64, 256 / 128, BB), blk>>>(attng, w_proj_g, b_proj_g, gg,
                                                                   256, SG, 256L * SG, 256L * SG, 0);
    upsample_kernel<<<(BB * CC * SL + 255) / 256, 256>>>(gg, concat);

    // fusion head (TC GEMMs)
    gemm_tc_kernel<1><<<dim3(SL / 64, 256 / 128, BB), 128>>>(concat, wh + WOFF_F1, wl + WOFF_F1,
                                                             b_f1, hbuf, 512, SL, 512L * SL, 256L * SL);
    gemm_tc_kernel<0><<<dim3(SL / 64, 256 / 128, BB), 128>>>(hbuf, wh + WOFF_F2, wl + WOFF_F2,
                                                             b_f2, out, 256, SL, 256L * SL, 256L * SL);
}

// round 14
// speedup vs baseline: 1.3375x; 1.1471x over previous
#include <cuda_runtime.h>
#include <cuda_bf16.h>
#include <math.h>

#define BB    4
#define CC    256
#define SL    2304     // 48*48
#define SG    144      // 12*12
#define HEADS 8
#define HD    32
#define SC    0.17677669529663687f

typedef unsigned long long u64;
typedef unsigned int u32;

// ---------------- helpers ----------------
__device__ __forceinline__ u64 ffma2(u64 a, u64 b, u64 c) {
    u64 d;
    asm("fma.rn.f32x2 %0, %1, %2, %3;" : "=l"(d) : "l"(a), "l"(b), "l"(c));
    return d;
}
__device__ __forceinline__ u64 pack2(float x, float y) {
    u64 d;
    asm("mov.b64 %0, {%1, %2};" : "=l"(d) : "f"(x), "f"(y));
    return d;
}
__device__ __forceinline__ float2 unpack2(u64 v) {
    float2 r;
    asm("mov.b64 {%0, %1}, %2;" : "=f"(r.x), "=f"(r.y) : "l"(v));
    return r;
}
__device__ __forceinline__ void lds2(const float* p, u64& a, u64& b) {
    double2 t = *(const double2*)p;
    a = (u64)__double_as_longlong(t.x);
    b = (u64)__double_as_longlong(t.y);
}
__device__ __forceinline__ u32 pack_bf16x2(float lo, float hi) {
    u32 r;
    asm("cvt.rn.bf16x2.f32 %0, %1, %2;" : "=r"(r) : "f"(hi), "f"(lo));
    return r;
}
__device__ __forceinline__ u32 bf16_bits(float x) {
    u32 r;
    asm("cvt.rn.bf16x2.f32 %0, %1, %2;" : "=r"(r) : "f"(0.f), "f"(x));
    return r & 0xFFFFu;
}
__device__ __forceinline__ void split2(float x, float y, u32& hi, u32& lo) {
    u32 hx = bf16_bits(x), hy = bf16_bits(y);
    hi = hx | (hy << 16);
    float fx = __uint_as_float(hx << 16);
    float fy = __uint_as_float(hy << 16);
    lo = pack_bf16x2(x - fx, y - fy);
}
__device__ __forceinline__ void mma16816(float* c, const u32* a, const u32* b) {
    asm volatile("mma.sync.aligned.m16n8k16.row.col.f32.bf16.bf16.f32 "
        "{%0,%1,%2,%3}, {%4,%5,%6,%7}, {%8,%9}, {%0,%1,%2,%3};"
        : "+f"(c[0]), "+f"(c[1]), "+f"(c[2]), "+f"(c[3])
        : "r"(a[0]), "r"(a[1]), "r"(a[2]), "r"(a[3]), "r"(b[0]), "r"(b[1]));
}

// ---------------- scratch ----------------
__device__ float g_qkv   [BB*768*SL];
__device__ float g_attn  [BB*CC*SL];
__device__ float g_concat[(long)BB*512*SL];
__device__ float g_h     [BB*CC*SL];
__device__ float g_xc    [BB*CC*SG];
__device__ float g_qkvg  [BB*768*SG];
__device__ float g_qkvtg [BB*768*SG];
__device__ float g_attng [BB*CC*SG];
__device__ float g_g     [BB*CC*SG];
__device__ __nv_bfloat16 g_vt[BB*HEADS*32*SL];   // V^T bf16 [b,h,d,s]
__device__ u32 g_kb[BB*HEADS*SL*16];             // K bf16x2 d-pairs [b,h,s,16]
__device__ u32 g_qb[BB*HEADS*SL*16];             // Q*SC bf16x2 d-pairs
__device__ float g_vsum[BB*HEADS*32];
#define WOFF_QKV  0
#define WOFF_PROJ 98304
#define WOFF_F1   131072
#define WOFF_F2   196608
#define WTOT      229376
__device__ u32 g_wh[WTOT];
__device__ u32 g_wl[WTOT];

// ---------------- combined weight split ----------------
__global__ void wsplit_all_kernel(const float* __restrict__ Wq, const float* __restrict__ Wp,
                                  const float* __restrict__ Wf1, const float* __restrict__ Wf2,
                                  u32* __restrict__ Wh, u32* __restrict__ Wl)
{
    int i = blockIdx.x * blockDim.x + threadIdx.x;
    if (i >= WTOT) return;
    const float* src;
    int off;
    if (i < WOFF_PROJ)      { src = Wq;  off = i - WOFF_QKV; }
    else if (i < WOFF_F1)   { src = Wp;  off = i - WOFF_PROJ; }
    else if (i < WOFF_F2)   { src = Wf1; off = i - WOFF_F1; }
    else                    { src = Wf2; off = i - WOFF_F2; }
    float x = src[2 * off], y = src[2 * off + 1];
    u32 h, l;
    split2(x, y, h, l);
    Wh[i] = h; Wl[i] = l;
}

// ---------------- TC conv1x1 GEMM: 128o x 128s tile, 256 threads, prefetch ----------------
template<int GELU>
__global__ void __launch_bounds__(256, 2)
gemm_tc_kernel(const float* __restrict__ X, const u32* __restrict__ Wh,
               const u32* __restrict__ Wl, const float* __restrict__ bias,
               float* __restrict__ Y, int Cin, int Ssz, long xBS, long yBS)
{
    __shared__ u32 sWh[128][12], sWl[128][12];
    __shared__ u32 sXh[128][12], sXl[128][12];
    const int tid = threadIdx.x;
    const int w = tid >> 5, lane = tid & 31;
    const int g = lane >> 2, t = lane & 3;
    const int ow = w >> 2, sq = w & 3;     // warp -> o-half, s-quarter
    const int s0 = blockIdx.x * 128;
    const int o0 = blockIdx.y * 128;
    const int b  = blockIdx.z;
    const float* Xb = X + (long)b * xBS;
    const int cp = Cin >> 1;

    // staging maps
    const int wrow = tid >> 1, whf = (tid & 1) * 4;   // W: row, 4-u32 half
    const int xsr = tid & 127, xcg = tid >> 7;        // X: s index, cpair group (0/1)

    float acc[4][4][4];
    #pragma unroll
    for (int m = 0; m < 4; m++)
        #pragma unroll
        for (int n = 0; n < 4; n++)
            #pragma unroll
            for (int i = 0; i < 4; i++) acc[m][n][i] = 0.f;

    uint4 pwh, pwl;
    float px[8];
    // preload chunk 0
    {
        pwh = *(const uint4*)(Wh + (long)(o0 + wrow) * cp + whf);
        pwl = *(const uint4*)(Wl + (long)(o0 + wrow) * cp + whf);
        const float* xb0 = Xb + (long)(xcg * 8) * Ssz + s0 + xsr;
        #pragma unroll
        for (int j = 0; j < 8; j++) px[j] = xb0[(long)j * Ssz];
    }

    for (int c0 = 0; c0 < Cin; c0 += 16) {
        // store prefetched regs to smem
        *(uint4*)&sWh[wrow][whf] = pwh;
        *(uint4*)&sWl[wrow][whf] = pwl;
        #pragma unroll
        for (int j = 0; j < 4; j++) {
            u32 h, l;
            split2(px[2 * j], px[2 * j + 1], h, l);
            sXh[xsr][xcg * 4 + j] = h;
            sXl[xsr][xcg * 4 + j] = l;
        }
        __syncthreads();

        // prefetch next chunk
        if (c0 + 16 < Cin) {
            int cn = c0 + 16;
            pwh = *(const uint4*)(Wh + (long)(o0 + wrow) * cp + (cn >> 1) + whf);
            pwl = *(const uint4*)(Wl + (long)(o0 + wrow) * cp + (cn >> 1) + whf);
            const float* xb0 = Xb + (long)(cn + xcg * 8) * Ssz + s0 + xsr;
            #pragma unroll
            for (int j = 0; j < 8; j++) px[j] = xb0[(long)j * Ssz];
        }

        // compute: m-outer (low register pressure)
        #pragma unroll
        for (int m = 0; m < 4; m++) {
            int ro = ow * 64 + m * 16;
            u32 ah[4], al[4];
            ah[0] = sWh[ro + g][t];         al[0] = sWl[ro + g][t];
            ah[1] = sWh[ro + g + 8][t];     al[1] = sWl[ro + g + 8][t];
            ah[2] = sWh[ro + g][t + 4];     al[2] = sWl[ro + g][t + 4];
            ah[3] = sWh[ro + g + 8][t + 4]; al[3] = sWl[ro + g + 8][t + 4];
            #pragma unroll
            for (int n = 0; n < 4; n++) {
                int xr = sq * 32 + n * 8 + g;
                u32 bh[2] = { sXh[xr][t], sXh[xr][t + 4] };
                u32 bl[2] = { sXl[xr][t], sXl[xr][t + 4] };
                mma16816(acc[m][n], ah, bh);
                mma16816(acc[m][n], al, bh);
                mma16816(acc[m][n], ah, bl);
            }
        }
        __syncthreads();
    }

    #pragma unroll
    for (int m = 0; m < 4; m++) {
        int o = o0 + ow * 64 + m * 16 + g;
        float bv0 = bias ? bias[o] : 0.f;
        float bv1 = bias ? bias[o + 8] : 0.f;
        long base0 = (long)b * yBS + (long)o * Ssz;
        long base1 = base0 + 8L * Ssz;
        #pragma unroll
        for (int n = 0; n < 4; n++) {
            int s = s0 + sq * 32 + n * 8 + 2 * t;
            float y00 = acc[m][n][0] + bv0, y01 = acc[m][n][1] + bv0;
            float y10 = acc[m][n][2] + bv1, y11 = acc[m][n][3] + bv1;
            if (GELU) {
                y00 = 0.5f * y00 * (1.f + erff(y00 * 0.70710678118654752f));
                y01 = 0.5f * y01 * (1.f + erff(y01 * 0.70710678118654752f));
                y10 = 0.5f * y10 * (1.f + erff(y10 * 0.70710678118654752f));
                y11 = 0.5f * y11 * (1.f + erff(y11 * 0.70710678118654752f));
            }
            *(float2*)&Y[base0 + s] = make_float2(y00, y01);
            *(float2*)&Y[base1 + s] = make_float2(y10, y11);
        }
    }
}

// ---------------- SIMT conv1x1 GEMM (global branch only) ----------------
template<int BM>
__global__ void __launch_bounds__(256)
gemm_kernel(const float* __restrict__ X, const float* __restrict__ Wm,
            const float* __restrict__ bias, float* __restrict__ Y,
            int Cin, int Ssz, long xBS, long yBS, int doGelu)
{
    constexpr int MR = BM / 16;
    constexpr int TPO = 16 / MR;
    __shared__ __align__(16) float Ws[16][BM];
    __shared__ __align__(16) float Xs[16][64];
    const int tx = threadIdx.x, ty = threadIdx.y;
    const int tid = ty * 16 + tx;
    const int s0 = blockIdx.x * 64;
    const int o0 = blockIdx.y * BM;
    const int b  = blockIdx.z;
    const float* Xb = X + (long)b * xBS;
    const bool full = (s0 + 64 <= Ssz);

    const int lw_o = tid / TPO;
    const int lw_c = (tid % TPO) * MR;
    const int lx_c = tid >> 4;
    const int lx_s = (tid & 15) * 4;

    u64 acc[MR][2];
    #pragma unroll
    for (int i = 0; i < MR; i++) { acc[i][0] = 0ULL; acc[i][1] = 0ULL; }

    for (int c0 = 0; c0 < Cin; c0 += 16) {
        {
            const float* wrow = Wm + (long)(o0 + lw_o) * Cin + c0 + lw_c;
            #pragma unroll
            for (int r = 0; r < MR; r += 4) {
                float4 w = *(const float4*)(wrow + r);
                Ws[lw_c + r + 0][lw_o] = w.x; Ws[lw_c + r + 1][lw_o] = w.y;
                Ws[lw_c + r + 2][lw_o] = w.z; Ws[lw_c + r + 3][lw_o] = w.w;
            }
        }
        {
            const float* xrow = Xb + (long)(c0 + lx_c) * Ssz + s0 + lx_s;
            if (full) {
                float4 xv = *(const float4*)xrow;
                Xs[lx_c][lx_s + 0] = xv.x; Xs[lx_c][lx_s + 1] = xv.y;
                Xs[lx_c][lx_s + 2] = xv.z; Xs[lx_c][lx_s + 3] = xv.w;
            } else {
                #pragma unroll
                for (int i = 0; i < 4; i++)
                    Xs[lx_c][lx_s + i] = (s0 + lx_s + i < Ssz) ? xrow[i] : 0.f;
            }
        }
        __syncthreads();

        #pragma unroll
        for (int c = 0; c < 16; c++) {
            u64 x01, x23;
            lds2(&Xs[c][tx * 4], x01, x23);
            #pragma unroll
            for (int r = 0; r < MR; r += 4) {
                float4 a = *(const float4*)&Ws[c][ty * MR + r];
                u64 p;
                p = pack2(a.x, a.x); acc[r+0][0] = ffma2(p, x01, acc[r+0][0]); acc[r+0][1] = ffma2(p, x23, acc[r+0][1]);
                p = pack2(a.y, a.y); acc[r+1][0] = ffma2(p, x01, acc[r+1][0]); acc[r+1][1] = ffma2(p, x23, acc[r+1][1]);
                p = pack2(a.z, a.z); acc[r+2][0] = ffma2(p, x01, acc[r+2][0]); acc[r+2][1] = ffma2(p, x23, acc[r+2][1]);
                p = pack2(a.w, a.w); acc[r+3][0] = ffma2(p, x01, acc[r+3][0]); acc[r+3][1] = ffma2(p, x23, acc[r+3][1]);
            }
        }
        __syncthreads();
    }

    #pragma unroll
    for (int i = 0; i < MR; i++) {
        int o = o0 + ty * MR + i;
        float bv = bias ? bias[o] : 0.f;
        float2 p0 = unpack2(acc[i][0]);
        float2 p1 = unpack2(acc[i][1]);
        float vals[4] = {p0.x, p0.y, p1.x, p1.y};
        #pragma unroll
        for (int j = 0; j < 4; j++) {
            int s = s0 + tx * 4 + j;
            if (s < Ssz) {
                float v = vals[j] + bv;
                if (doGelu) v = 0.5f * v * (1.f + erff(v * 0.70710678118654752f));
                Y[(long)b * yBS + (long)o * Ssz + s] = v;
            }
        }
    }
}

// ---- tnorm: local branch -> qb/kb/vt/vsum (bf16 only); global -> fp32 qkvt ----
__global__ void tnorm_kernel(const float* __restrict__ qkv, float* __restrict__ qkvt, int Ssz,
                             __nv_bfloat16* __restrict__ vt, float* __restrict__ vsum,
                             u32* __restrict__ kb, u32* __restrict__ qb, int doAux)
{
    __shared__ float sm[32][33];
    const int bp = blockIdx.y;
    const int b = bp / 24;
    const int rem = bp % 24;
    const int part = rem / 8;
    const int h = rem % 8;
    const int s0 = blockIdx.x * 32;
    const int tx = threadIdx.x, ty = threadIdx.y;

    {
        int s = s0 + tx;
        float v = 0.f;
        if (s < Ssz) v = qkv[((long)b * 768 + part * 256 + h * 32 + ty) * Ssz + s];
        sm[ty][tx] = v;
    }
    __syncthreads();

    if (doAux && part == 2) {
        float vo = sm[ty][tx];
        int s = s0 + tx;
        if (s < Ssz)
            vt[((long)(b * HEADS + h) * 32 + ty) * Ssz + s] = __float2bfloat16(vo);
        float sum = (s < Ssz) ? vo : 0.f;
        #pragma unroll
        for (int off = 16; off; off >>= 1) sum += __shfl_xor_sync(0xffffffffu, sum, off);
        if (tx == 0) atomicAdd(&vsum[(b * HEADS + h) * 32 + ty], sum);
    }

    float v = sm[tx][ty];   // value at (d = tx, s = s0 + ty)
    if (part < 2) {
        float sq = v * v;
        #pragma unroll
        for (int off = 16; off; off >>= 1) sq += __shfl_xor_sync(0xffffffffu, sq, off);
        float n = sqrtf(sq);
        v = v / fmaxf(n, 1e-12f);
    }
    int s = s0 + ty;

    if (doAux) {
        if (part == 0) {
            float vq = v * SC;
            float vhi = __shfl_down_sync(0xffffffffu, vq, 1);
            if ((tx & 1) == 0 && s < Ssz)
                qb[((long)(b * HEADS + h) * SL + s) * 16 + (tx >> 1)] = pack_bf16x2(vq, vhi);
        } else if (part == 1) {
            float vhi = __shfl_down_sync(0xffffffffu, v, 1);
            if ((tx & 1) == 0 && s < Ssz)
                kb[((long)(b * HEADS + h) * SL + s) * 16 + (tx >> 1)] = pack_bf16x2(v, vhi);
        }
        // part == 2 handled above (vt); no fp32 stores for local branch
    } else {
        if (s < Ssz)
            qkvt[(((long)(b * 3 + part) * 8 + h) * Ssz + s) * 32 + tx] = v;
    }
}

// ---------------- mma.sync bf16 flash attention (local branch) ----------------
__global__ void __launch_bounds__(128, 4)
attn_tc_kernel(const u32* __restrict__ qb, const u32* __restrict__ kb,
               const __nv_bfloat16* __restrict__ vt,
               const float* __restrict__ vsum, float* __restrict__ out)
{
    __shared__ u32 Ks[64][36];
    __shared__ u32 Vs[32][36];
    const int tid = threadIdx.x;
    const int w = tid >> 5, lane = tid & 31;
    const int g = lane >> 2, t = lane & 3;
    const int bh = blockIdx.x;
    const int b = bh >> 3, h = bh & 7;
    const int q0 = blockIdx.y * 128;
    const u32* Qb = qb + (long)bh * SL * 16;
    const u32* Kb = kb + (long)bh * SL * 16;
    const char* Vg = (const char*)(vt + (long)bh * 32 * SL);

    u32 qa[2][2][4];
    #pragma unroll
    for (int m = 0; m < 2; m++) {
        long r0 = q0 + w * 32 + m * 16 + g;
        #pragma unroll
        for (int kt = 0; kt < 2; kt++) {
            int cp = kt * 8 + t;
            qa[m][kt][0] = Qb[r0 * 16 + cp];
            qa[m][kt][1] = Qb[(r0 + 8) * 16 + cp];
            qa[m][kt][2] = Qb[r0 * 16 + cp + 4];
            qa[m][kt][3] = Qb[(r0 + 8) * 16 + cp + 4];
        }
    }

    float oacc[2][4][4];
    #pragma unroll
    for (int m = 0; m < 2; m++)
        #pragma unroll
        for (int j = 0; j < 4; j++)
            #pragma unroll
            for (int i = 0; i < 4; i++) oacc[m][j][i] = 0.f;
    float lrow[2][2] = {{0.f, 0.f}, {0.f, 0.f}};

    for (int blk = 0; blk < 36; blk++) {
        const int k0 = blk * 64;
        {
            int r = tid >> 1, hf = (tid & 1) * 8;
            const uint4* kp = (const uint4*)(Kb + ((long)(k0 + r) * 16 + hf));
            uint4 k0v = kp[0], k1v = kp[1];
            u32* kd = &Ks[r][hf];
            kd[0] = k0v.x; kd[1] = k0v.y; kd[2] = k0v.z; kd[3] = k0v.w;
            kd[4] = k1v.x; kd[5] = k1v.y; kd[6] = k1v.z; kd[7] = k1v.w;
        }
        {
            int r = tid >> 2, s4 = tid & 3;
            const uint4* vr = (const uint4*)(Vg + (long)r * (SL * 2) + k0 * 2 + s4 * 32);
            uint4 v0 = vr[0], v1 = vr[1];
            u32* vd = &Vs[r][s4 * 8];
            vd[0] = v0.x; vd[1] = v0.y; vd[2] = v0.z; vd[3] = v0.w;
            vd[4] = v1.x; vd[5] = v1.y; vd[6] = v1.z; vd[7] = v1.w;
        }
        __syncthreads();

        #pragma unroll
        for (int hf = 0; hf < 2; hf++) {
            float sacc[2][4][4];
            #pragma unroll
            for (int m = 0; m < 2; m++)
                #pragma unroll
                for (int j = 0; j < 4; j++)
                    #pragma unroll
                    for (int i = 0; i < 4; i++) sacc[m][j][i] = 0.f;

            #pragma unroll
            for (int kt = 0; kt < 2; kt++)
                #pragma unroll
                for (int j = 0; j < 4; j++) {
                    int jj = hf * 4 + j;
                    u32 bb[2] = { Ks[8 * jj + g][kt * 8 + t], Ks[8 * jj + g][kt * 8 + t + 4] };
                    mma16816(sacc[0][j], qa[0][kt], bb);
                    mma16816(sacc[1][j], qa[1][kt], bb);
                }

            u32 fa[2][2][4];
            #pragma unroll
            for (int m = 0; m < 2; m++)
                #pragma unroll
                for (int j = 0; j < 4; j++) {
                    float p0 = __expf(sacc[m][j][0]);
                    float p1 = __expf(sacc[m][j][1]);
                    float p2 = __expf(sacc[m][j][2]);
                    float p3 = __expf(sacc[m][j][3]);
                    lrow[m][0] += p0 + p1;
                    lrow[m][1] += p2 + p3;
                    int kkl = j >> 1, hi2 = (j & 1) * 2;
                    fa[m][kkl][hi2 + 0] = pack_bf16x2(p0 - 1.f, p1 - 1.f);
                    fa[m][kkl][hi2 + 1] = pack_bf16x2(p2 - 1.f, p3 - 1.f);
                }

            #pragma unroll
            for (int kkl = 0; kkl < 2; kkl++) {
                int kk = hf * 2 + kkl;
                #pragma unroll
                for (int jn = 0; jn < 4; jn++) {
                    u32 bb[2] = { Vs[8 * jn + g][kk * 8 + t], Vs[8 * jn + g][kk * 8 + t + 4] };
                    mma16816(oacc[0][jn], fa[0][kkl], bb);
                    mma16816(oacc[1][jn], fa[1][kkl], bb);
                }
            }
        }
        __syncthreads();
    }

    #pragma unroll
    for (int m = 0; m < 2; m++)
        #pragma unroll
        for (int rh = 0; rh < 2; rh++) {
            float l = lrow[m][rh];
            l += __shfl_xor_sync(0xffffffffu, l, 1);
            l += __shfl_xor_sync(0xffffffffu, l, 2);
            lrow[m][rh] = l;
        }

    const float* vs = vsum + bh * 32;
    long ob = (long)b * CC + h * HD;
    #pragma unroll
    for (int m = 0; m < 2; m++)
        #pragma unroll
        for (int rh = 0; rh < 2; rh++) {
            float inv = 1.f / lrow[m][rh];
            int row = q0 + w * 32 + m * 16 + g + rh * 8;
            #pragma unroll
            for (int jn = 0; jn < 4; jn++) {
                int d = 8 * jn + 2 * t;
                float v0 = (__ldg(vs + d)     + oacc[m][jn][rh * 2 + 0]) * inv;
                float v1 = (__ldg(vs + d + 1) + oacc[m][jn][rh * 2 + 1]) * inv;
                out[(ob + d)     * (long)SL + row] = v0;
                out[(ob + d + 1) * (long)SL + row] = v1;
            }
        }
}

// ---------------- SIMT flash attention (global branch, S=144) ----------------
__global__ void __launch_bounds__(128, 2)
attn_kernel(const float* __restrict__ qkvt, float* __restrict__ out, int Ssz)
{
    __shared__ __align__(16) float ks[64][32];
    __shared__ __align__(16) float vs[64][32];
    const int bh = blockIdx.x;
    const int b = bh >> 3, h = bh & 7;
    const long base = ((long)(b * 3) * HEADS + h) * Ssz * HD;
    const float* Q = qkvt + base;
    const float* K = Q + (long)HEADS * Ssz * HD;
    const float* V = Q + 2L * HEADS * Ssz * HD;
    const int tid = threadIdx.x;
    const int rowa = blockIdx.y * 256 + tid;
    const int rowb = rowa + 128;
    const bool va = rowa < Ssz;
    const bool vb = rowb < Ssz;

    const u64 sc2 = pack2(SC, SC);

    u64 qa[16], qb2[16];
    #pragma unroll
    for (int i = 0; i < 16; i++) { qa[i] = 0ULL; qb2[i] = 0ULL; }
    if (va) {
        #pragma unroll
        for (int i = 0; i < 8; i++) {
            u64 t0, t1;
            lds2(Q + (long)rowa * 32 + i * 4, t0, t1);
            qa[2 * i] = ffma2(t0, sc2, 0ULL);
            qa[2 * i + 1] = ffma2(t1, sc2, 0ULL);
        }
    }
    if (vb) {
        #pragma unroll
        for (int i = 0; i < 8; i++) {
            u64 t0, t1;
            lds2(Q + (long)rowb * 32 + i * 4, t0, t1);
            qb2[2 * i] = ffma2(t0, sc2, 0ULL);
            qb2[2 * i + 1] = ffma2(t1, sc2, 0ULL);
        }
    }

    u64 aa[16], ab[16];
    #pragma unroll
    for (int i = 0; i < 16; i++) { aa[i] = 0ULL; ab[i] = 0ULL; }
    float la = 0.f, lb = 0.f;

    for (int j0 = 0; j0 < Ssz; j0 += 64) {
        int cnt = min(64, Ssz - j0);
        int nf4 = cnt * 8;
        const float4* kp = (const float4*)(K + (long)j0 * 32);
        const float4* vp = (const float4*)(V + (long)j0 * 32);
        #pragma unroll
        for (int t = 0; t < 4; t++) {
            int i = tid + t * 128;
            if (i < nf4) { ((float4*)ks)[i] = kp[i]; ((float4*)vs)[i] = vp[i]; }
        }
        __syncthreads();
        for (int j = 0; j < cnt; j++) {
            u64 kt[16];
            #pragma unroll
            for (int i = 0; i < 8; i++) lds2(&ks[j][i * 4], kt[2 * i], kt[2 * i + 1]);
            u64 da0 = 0ULL, da1 = 0ULL, db0 = 0ULL, db1 = 0ULL;
            #pragma unroll
            for (int i = 0; i < 16; i += 2) {
                da0 = ffma2(qa[i], kt[i], da0);
                da1 = ffma2(qa[i + 1], kt[i + 1], da1);
                db0 = ffma2(qb2[i], kt[i], db0);
                db1 = ffma2(qb2[i + 1], kt[i + 1], db1);
            }
            float2 ea0 = unpack2(da0), ea1 = unpack2(da1);
            float2 eb0 = unpack2(db0), eb1 = unpack2(db1);
            float pa = __expf((ea0.x + ea0.y) + (ea1.x + ea1.y));
            float pb = __expf((eb0.x + eb0.y) + (eb1.x + eb1.y));
            la += pa; lb += pb;
            u64 pa2 = pack2(pa, pa);
            u64 pb2 = pack2(pb, pb);
            u64 vt2[16];
            #pragma unroll
            for (int i = 0; i < 8; i++) lds2(&vs[j][i * 4], vt2[2 * i], vt2[2 * i + 1]);
            #pragma unroll
            for (int i = 0; i < 16; i++) {
                aa[i] = ffma2(pa2, vt2[i], aa[i]);
                ab[i] = ffma2(pb2, vt2[i], ab[i]);
            }
        }
        __syncthreads();
    }

    long ob = (long)b * CC + h * HD;
    if (va) {
        float inv = 1.f / la;
        #pragma unroll
        for (int i = 0; i < 16; i++) {
            float2 t = unpack2(aa[i]);
            out[(ob + 2 * i) * (long)Ssz + rowa] = t.x * inv;
            out[(ob + 2 * i + 1) * (long)Ssz + rowa] = t.y * inv;
        }
    }
    if (vb) {
        float inv = 1.f / lb;
        #pragma unroll
        for (int i = 0; i < 16; i++) {
            float2 t = unpack2(ab[i]);
            out[(ob + 2 * i) * (long)Ssz + rowb] = t.x * inv;
            out[(ob + 2 * i + 1) * (long)Ssz + rowb] = t.y * inv;
        }
    }
}

// ---------------- 4x4 average pool ----------------
__global__ void avgpool_kernel(const float* __restrict__ x, float* __restrict__ xc)
{
    int idx = blockIdx.x * blockDim.x + threadIdx.x;
    if (idx >= BB * CC * SG) return;
    int p = idx % SG;
    int c = (idx / SG) % CC;
    int b = idx / (SG * CC);
    int i = p / 12, j = p % 12;
    const float* xp = x + ((long)b * CC + c) * SL;
    float s = 0.f;
    #pragma unroll
    for (int dy = 0; dy < 4; dy++)
        #pragma unroll
        for (int dx = 0; dx < 4; dx++)
            s += xp[(i * 4 + dy) * 48 + j * 4 + dx];
    xc[idx] = s * (1.f / 16.f);
}

// ---------------- bilinear upsample into concat ch 256..511 ----------------
__global__ void upsample_kernel(const float* __restrict__ g, float* __restrict__ concat)
{
    int idx = blockIdx.x * blockDim.x + threadIdx.x;
    if (idx >= BB * CC * SL) return;
    int p = idx % SL;
    int c = (idx / SL) % CC;
    int b = idx / (SL * CC);
    int y = p / 48, x = p % 48;
    float fy = (y + 0.5f) * 0.25f - 0.5f;
    float fx = (x + 0.5f) * 0.25f - 0.5f;
    int y0 = (int)floorf(fy), x0 = (int)floorf(fx);
    float wy = fy - y0, wx = fx - x0;
    int ya = min(11, max(0, y0)), yb = min(11, max(0, y0 + 1));
    int xa = min(11, max(0, x0)), xb = min(11, max(0, x0 + 1));
    const float* gp = g + ((long)b * CC + c) * SG;
    float v00 = gp[ya * 12 + xa], v01 = gp[ya * 12 + xb];
    float v10 = gp[yb * 12 + xa], v11 = gp[yb * 12 + xb];
    float v = (1.f - wy) * ((1.f - wx) * v00 + wx * v01)
            +        wy  * ((1.f - wx) * v10 + wx * v11);
    concat[((long)b * 512 + 256 + c) * SL + p] = v;
}

// ---------------- launch ----------------
extern "C" void kernel_launch(void* const* d_in, const int* in_sizes, int n_in,
                              void* d_out, int out_size)
{
    const float* x        = (const float*)d_in[0];
    const float* w_qkv_l  = (const float*)d_in[1];
    const float* w_proj_l = (const float*)d_in[2];
    const float* b_proj_l = (const float*)d_in[3];
    const float* w_qkv_g  = (const float*)d_in[4];
    const float* w_proj_g = (const float*)d_in[5];
    const float* b_proj_g = (const float*)d_in[6];
    const float* w_f1     = (const float*)d_in[7];
    const float* b_f1     = (const float*)d_in[8];
    const float* w_f2     = (const float*)d_in[9];
    const float* b_f2     = (const float*)d_in[10];
    float* out = (float*)d_out;

    float *qkv, *attn, *concat, *hbuf, *xc, *qkvg, *qkvtg, *attng, *gg, *vsum;
    __nv_bfloat16* vt;
    u32 *wh, *wl, *kb, *qb;
    cudaGetSymbolAddress((void**)&qkv,    g_qkv);
    cudaGetSymbolAddress((void**)&attn,   g_attn);
    cudaGetSymbolAddress((void**)&concat, g_concat);
    cudaGetSymbolAddress((void**)&hbuf,   g_h);
    cudaGetSymbolAddress((void**)&xc,     g_xc);
    cudaGetSymbolAddress((void**)&qkvg,   g_qkvg);
    cudaGetSymbolAddress((void**)&qkvtg,  g_qkvtg);
    cudaGetSymbolAddress((void**)&attng,  g_attng);
    cudaGetSymbolAddress((void**)&gg,     g_g);
    cudaGetSymbolAddress((void**)&vt,     g_vt);
    cudaGetSymbolAddress((void**)&vsum,   g_vsum);
    cudaGetSymbolAddress((void**)&wh,     g_wh);
    cudaGetSymbolAddress((void**)&wl,     g_wl);
    cudaGetSymbolAddress((void**)&kb,     g_kb);
    cudaGetSymbolAddress((void**)&qb,     g_qb);

    dim3 blk(16, 16);

    cudaMemsetAsync(vsum, 0, BB * HEADS * 32 * sizeof(float));
    wsplit_all_kernel<<<(WTOT + 255) / 256, 256>>>(w_qkv_l, w_proj_l, w_f1, w_f2, wh, wl);

    // local branch (TC; SL % 128 == 0 so all tiles full)
    gemm_tc_kernel<0><<<dim3(SL / 128, 768 / 128, BB), 256>>>(x, wh + WOFF_QKV, wl + WOFF_QKV,
                                                              nullptr, qkv, 256, SL, 256L * SL, 768L * SL);
    tnorm_kernel<<<dim3(SL / 32, BB * 24), dim3(32, 32)>>>(qkv, nullptr, SL, vt, vsum, kb, qb, 1);
    attn_tc_kernel<<<dim3(BB * HEADS, SL / 128), 128>>>(qb, kb, vt, vsum, attn);
    gemm_tc_kernel<0><<<dim3(SL / 128, 256 / 128, BB), 256>>>(attn, wh + WOFF_PROJ, wl + WOFF_PROJ,
                                                              b_proj_l, concat, 256, SL, 256L * SL, 512L * SL);

    // global branch (tiny; SIMT)
    avgpool_kernel<<<(BB * CC * SG + 255) / 256, 256>>>(x, xc);
    gemm_kernel<128><<<dim3((SG + 63) / 64, 768 / 128, BB), blk>>>(xc, w_qkv_g, nullptr, qkvg,
                                                                   256, SG, 256L * SG, 768L * SG, 0);
    tnorm_kernel<<<dim3((SG + 31) / 32, BB * 24), dim3(32, 32)>>>(qkvg, qkvtg, SG, vt, vsum, kb, qb, 0);
    attn_kernel<<<dim3(BB * HEADS, (SG + 255) / 256), 128>>>(qkvtg, attng, SG);
    gemm_kernel<128><<<dim3((SG + 63) / 64, 256 / 128, BB), blk>>>(attng, w_proj_g, b_proj_g, gg,
                                                                   256, SG, 256L * SG, 256L * SG, 0);
    upsample_kernel<<<(BB * CC * SL + 255) / 256, 256>>>(gg, concat);

    // fusion head (TC)
    gemm_tc_kernel<1><<<dim3(SL / 128, 256 / 128, BB), 256>>>(concat, wh + WOFF_F1, wl + WOFF_F1,
                                                              b_f1, hbuf, 512, SL, 512L * SL, 256L * SL);
    gemm_tc_kernel<0><<<dim3(SL / 128, 256 / 128, BB), 256>>>(hbuf, wh + WOFF_F2, wl + WOFF_F2,
                                                              b_f2, out, 256, SL, 256L * SL, 256L * SL);
}

// round 15
// speedup vs baseline: 1.5539x; 1.1618x over previous
#include <cuda_runtime.h>
#include <cuda_bf16.h>
#include <math.h>

#define BB    4
#define CC    256
#define SL    2304     // 48*48
#define SG    144      // 12*12
#define HEADS 8
#define HD    32
#define SC    0.17677669529663687f

typedef unsigned long long u64;
typedef unsigned int u32;

// ---------------- helpers ----------------
__device__ __forceinline__ u64 ffma2(u64 a, u64 b, u64 c) {
    u64 d;
    asm("fma.rn.f32x2 %0, %1, %2, %3;" : "=l"(d) : "l"(a), "l"(b), "l"(c));
    return d;
}
__device__ __forceinline__ u64 pack2(float x, float y) {
    u64 d;
    asm("mov.b64 %0, {%1, %2};" : "=l"(d) : "f"(x), "f"(y));
    return d;
}
__device__ __forceinline__ float2 unpack2(u64 v) {
    float2 r;
    asm("mov.b64 {%0, %1}, %2;" : "=f"(r.x), "=f"(r.y) : "l"(v));
    return r;
}
__device__ __forceinline__ void lds2(const float* p, u64& a, u64& b) {
    double2 t = *(const double2*)p;
    a = (u64)__double_as_longlong(t.x);
    b = (u64)__double_as_longlong(t.y);
}
__device__ __forceinline__ u32 pack_bf16x2(float lo, float hi) {
    u32 r;
    asm("cvt.rn.bf16x2.f32 %0, %1, %2;" : "=r"(r) : "f"(hi), "f"(lo));
    return r;
}
__device__ __forceinline__ u32 bf16_bits(float x) {
    u32 r;
    asm("cvt.rn.bf16x2.f32 %0, %1, %2;" : "=r"(r) : "f"(0.f), "f"(x));
    return r & 0xFFFFu;
}
__device__ __forceinline__ void split2(float x, float y, u32& hi, u32& lo) {
    u32 hx = bf16_bits(x), hy = bf16_bits(y);
    hi = hx | (hy << 16);
    float fx = __uint_as_float(hx << 16);
    float fy = __uint_as_float(hy << 16);
    lo = pack_bf16x2(x - fx, y - fy);
}
__device__ __forceinline__ void mma16816(float* c, const u32* a, const u32* b) {
    asm volatile("mma.sync.aligned.m16n8k16.row.col.f32.bf16.bf16.f32 "
        "{%0,%1,%2,%3}, {%4,%5,%6,%7}, {%8,%9}, {%0,%1,%2,%3};"
        : "+f"(c[0]), "+f"(c[1]), "+f"(c[2]), "+f"(c[3])
        : "r"(a[0]), "r"(a[1]), "r"(a[2]), "r"(a[3]), "r"(b[0]), "r"(b[1]));
}

// ---------------- scratch ----------------
__device__ float g_qkv   [BB*768*SL];
__device__ float g_attn  [BB*CC*SL];
__device__ float g_concat[(long)BB*512*SL];
__device__ float g_h     [BB*CC*SL];
__device__ float g_xc    [BB*CC*SG];
__device__ float g_qkvg  [BB*768*SG];
__device__ float g_qkvtg [BB*768*SG];
__device__ float g_attng [BB*CC*SG];
__device__ float g_g     [BB*CC*SG];
__device__ __nv_bfloat16 g_vt[BB*HEADS*32*SL];   // V^T bf16 [b,h,d,s]
__device__ u32 g_kb[BB*HEADS*SL*16];             // K bf16x2 d-pairs [b,h,s,16]
__device__ u32 g_qb[BB*HEADS*SL*16];             // Q*SC bf16x2 d-pairs
__device__ float g_vsum[BB*HEADS*32];
#define WOFF_QKV  0
#define WOFF_PROJ 98304
#define WOFF_F1   131072
#define WOFF_F2   196608
#define WTOT      229376
__device__ u32 g_wh[WTOT];
__device__ u32 g_wl[WTOT];

// ---------------- combined weight split ----------------
__global__ void wsplit_all_kernel(const float* __restrict__ Wq, const float* __restrict__ Wp,
                                  const float* __restrict__ Wf1, const float* __restrict__ Wf2,
                                  u32* __restrict__ Wh, u32* __restrict__ Wl)
{
    int i = blockIdx.x * blockDim.x + threadIdx.x;
    if (i >= WTOT) return;
    const float* src;
    int off;
    if (i < WOFF_PROJ)      { src = Wq;  off = i - WOFF_QKV; }
    else if (i < WOFF_F1)   { src = Wp;  off = i - WOFF_PROJ; }
    else if (i < WOFF_F2)   { src = Wf1; off = i - WOFF_F1; }
    else                    { src = Wf2; off = i - WOFF_F2; }
    float x = src[2 * off], y = src[2 * off + 1];
    u32 h, l;
    split2(x, y, h, l);
    Wh[i] = h; Wl[i] = l;
}

// ---------------- TC conv1x1 GEMM: 128o x 128s tile, 256 threads, prefetch ----------------
template<int GELU>
__global__ void __launch_bounds__(256, 2)
gemm_tc_kernel(const float* __restrict__ X, const u32* __restrict__ Wh,
               const u32* __restrict__ Wl, const float* __restrict__ bias,
               float* __restrict__ Y, int Cin, int Ssz, long xBS, long yBS)
{
    __shared__ u32 sWh[128][12], sWl[128][12];
    __shared__ u32 sXh[128][12], sXl[128][12];
    const int tid = threadIdx.x;
    const int w = tid >> 5, lane = tid & 31;
    const int g = lane >> 2, t = lane & 3;
    const int ow = w >> 2, sq = w & 3;
    const int s0 = blockIdx.x * 128;
    const int o0 = blockIdx.y * 128;
    const int b  = blockIdx.z;
    const float* Xb = X + (long)b * xBS;
    const int cp = Cin >> 1;

    const int wrow = tid >> 1, whf = (tid & 1) * 4;
    const int xsr = tid & 127, xcg = tid >> 7;

    float acc[4][4][4];
    #pragma unroll
    for (int m = 0; m < 4; m++)
        #pragma unroll
        for (int n = 0; n < 4; n++)
            #pragma unroll
            for (int i = 0; i < 4; i++) acc[m][n][i] = 0.f;

    uint4 pwh, pwl;
    float px[8];
    {
        pwh = *(const uint4*)(Wh + (long)(o0 + wrow) * cp + whf);
        pwl = *(const uint4*)(Wl + (long)(o0 + wrow) * cp + whf);
        const float* xb0 = Xb + (long)(xcg * 8) * Ssz + s0 + xsr;
        #pragma unroll
        for (int j = 0; j < 8; j++) px[j] = xb0[(long)j * Ssz];
    }

    for (int c0 = 0; c0 < Cin; c0 += 16) {
        *(uint4*)&sWh[wrow][whf] = pwh;
        *(uint4*)&sWl[wrow][whf] = pwl;
        #pragma unroll
        for (int j = 0; j < 4; j++) {
            u32 h, l;
            split2(px[2 * j], px[2 * j + 1], h, l);
            sXh[xsr][xcg * 4 + j] = h;
            sXl[xsr][xcg * 4 + j] = l;
        }
        __syncthreads();

        if (c0 + 16 < Cin) {
            int cn = c0 + 16;
            pwh = *(const uint4*)(Wh + (long)(o0 + wrow) * cp + (cn >> 1) + whf);
            pwl = *(const uint4*)(Wl + (long)(o0 + wrow) * cp + (cn >> 1) + whf);
            const float* xb0 = Xb + (long)(cn + xcg * 8) * Ssz + s0 + xsr;
            #pragma unroll
            for (int j = 0; j < 8; j++) px[j] = xb0[(long)j * Ssz];
        }

        #pragma unroll
        for (int m = 0; m < 4; m++) {
            int ro = ow * 64 + m * 16;
            u32 ah[4], al[4];
            ah[0] = sWh[ro + g][t];         al[0] = sWl[ro + g][t];
            ah[1] = sWh[ro + g + 8][t];     al[1] = sWl[ro + g + 8][t];
            ah[2] = sWh[ro + g][t + 4];     al[2] = sWl[ro + g][t + 4];
            ah[3] = sWh[ro + g + 8][t + 4]; al[3] = sWl[ro + g + 8][t + 4];
            #pragma unroll
            for (int n = 0; n < 4; n++) {
                int xr = sq * 32 + n * 8 + g;
                u32 bh[2] = { sXh[xr][t], sXh[xr][t + 4] };
                u32 bl[2] = { sXl[xr][t], sXl[xr][t + 4] };
                mma16816(acc[m][n], ah, bh);
                mma16816(acc[m][n], al, bh);
                mma16816(acc[m][n], ah, bl);
            }
        }
        __syncthreads();
    }

    #pragma unroll
    for (int m = 0; m < 4; m++) {
        int o = o0 + ow * 64 + m * 16 + g;
        float bv0 = bias ? bias[o] : 0.f;
        float bv1 = bias ? bias[o + 8] : 0.f;
        long base0 = (long)b * yBS + (long)o * Ssz;
        long base1 = base0 + 8L * Ssz;
        #pragma unroll
        for (int n = 0; n < 4; n++) {
            int s = s0 + sq * 32 + n * 8 + 2 * t;
            float y00 = acc[m][n][0] + bv0, y01 = acc[m][n][1] + bv0;
            float y10 = acc[m][n][2] + bv1, y11 = acc[m][n][3] + bv1;
            if (GELU) {
                y00 = 0.5f * y00 * (1.f + erff(y00 * 0.70710678118654752f));
                y01 = 0.5f * y01 * (1.f + erff(y01 * 0.70710678118654752f));
                y10 = 0.5f * y10 * (1.f + erff(y10 * 0.70710678118654752f));
                y11 = 0.5f * y11 * (1.f + erff(y11 * 0.70710678118654752f));
            }
            *(float2*)&Y[base0 + s] = make_float2(y00, y01);
            *(float2*)&Y[base1 + s] = make_float2(y10, y11);
        }
    }
}

// ---------------- SIMT conv1x1 GEMM (global branch only) ----------------
template<int BM>
__global__ void __launch_bounds__(256)
gemm_kernel(const float* __restrict__ X, const float* __restrict__ Wm,
            const float* __restrict__ bias, float* __restrict__ Y,
            int Cin, int Ssz, long xBS, long yBS, int doGelu)
{
    constexpr int MR = BM / 16;
    constexpr int TPO = 16 / MR;
    __shared__ __align__(16) float Ws[16][BM];
    __shared__ __align__(16) float Xs[16][64];
    const int tx = threadIdx.x, ty = threadIdx.y;
    const int tid = ty * 16 + tx;
    const int s0 = blockIdx.x * 64;
    const int o0 = blockIdx.y * BM;
    const int b  = blockIdx.z;
    const float* Xb = X + (long)b * xBS;
    const bool full = (s0 + 64 <= Ssz);

    const int lw_o = tid / TPO;
    const int lw_c = (tid % TPO) * MR;
    const int lx_c = tid >> 4;
    const int lx_s = (tid & 15) * 4;

    u64 acc[MR][2];
    #pragma unroll
    for (int i = 0; i < MR; i++) { acc[i][0] = 0ULL; acc[i][1] = 0ULL; }

    for (int c0 = 0; c0 < Cin; c0 += 16) {
        {
            const float* wrow = Wm + (long)(o0 + lw_o) * Cin + c0 + lw_c;
            #pragma unroll
            for (int r = 0; r < MR; r += 4) {
                float4 w = *(const float4*)(wrow + r);
                Ws[lw_c + r + 0][lw_o] = w.x; Ws[lw_c + r + 1][lw_o] = w.y;
                Ws[lw_c + r + 2][lw_o] = w.z; Ws[lw_c + r + 3][lw_o] = w.w;
            }
        }
        {
            const float* xrow = Xb + (long)(c0 + lx_c) * Ssz + s0 + lx_s;
            if (full) {
                float4 xv = *(const float4*)xrow;
                Xs[lx_c][lx_s + 0] = xv.x; Xs[lx_c][lx_s + 1] = xv.y;
                Xs[lx_c][lx_s + 2] = xv.z; Xs[lx_c][lx_s + 3] = xv.w;
            } else {
                #pragma unroll
                for (int i = 0; i < 4; i++)
                    Xs[lx_c][lx_s + i] = (s0 + lx_s + i < Ssz) ? xrow[i] : 0.f;
            }
        }
        __syncthreads();

        #pragma unroll
        for (int c = 0; c < 16; c++) {
            u64 x01, x23;
            lds2(&Xs[c][tx * 4], x01, x23);
            #pragma unroll
            for (int r = 0; r < MR; r += 4) {
                float4 a = *(const float4*)&Ws[c][ty * MR + r];
                u64 p;
                p = pack2(a.x, a.x); acc[r+0][0] = ffma2(p, x01, acc[r+0][0]); acc[r+0][1] = ffma2(p, x23, acc[r+0][1]);
                p = pack2(a.y, a.y); acc[r+1][0] = ffma2(p, x01, acc[r+1][0]); acc[r+1][1] = ffma2(p, x23, acc[r+1][1]);
                p = pack2(a.z, a.z); acc[r+2][0] = ffma2(p, x01, acc[r+2][0]); acc[r+2][1] = ffma2(p, x23, acc[r+2][1]);
                p = pack2(a.w, a.w); acc[r+3][0] = ffma2(p, x01, acc[r+3][0]); acc[r+3][1] = ffma2(p, x23, acc[r+3][1]);
            }
        }
        __syncthreads();
    }

    #pragma unroll
    for (int i = 0; i < MR; i++) {
        int o = o0 + ty * MR + i;
        float bv = bias ? bias[o] : 0.f;
        float2 p0 = unpack2(acc[i][0]);
        float2 p1 = unpack2(acc[i][1]);
        float vals[4] = {p0.x, p0.y, p1.x, p1.y};
        #pragma unroll
        for (int j = 0; j < 4; j++) {
            int s = s0 + tx * 4 + j;
            if (s < Ssz) {
                float v = vals[j] + bv;
                if (doGelu) v = 0.5f * v * (1.f + erff(v * 0.70710678118654752f));
                Y[(long)b * yBS + (long)o * Ssz + s] = v;
            }
        }
    }
}

// ---- tnorm: local branch -> qb/kb/vt/vsum (bf16 only); global -> fp32 qkvt ----
__global__ void tnorm_kernel(const float* __restrict__ qkv, float* __restrict__ qkvt, int Ssz,
                             __nv_bfloat16* __restrict__ vt, float* __restrict__ vsum,
                             u32* __restrict__ kb, u32* __restrict__ qb, int doAux)
{
    __shared__ float sm[32][33];
    const int bp = blockIdx.y;
    const int b = bp / 24;
    const int rem = bp % 24;
    const int part = rem / 8;
    const int h = rem % 8;
    const int s0 = blockIdx.x * 32;
    const int tx = threadIdx.x, ty = threadIdx.y;

    {
        int s = s0 + tx;
        float v = 0.f;
        if (s < Ssz) v = qkv[((long)b * 768 + part * 256 + h * 32 + ty) * Ssz + s];
        sm[ty][tx] = v;
    }
    __syncthreads();

    if (doAux && part == 2) {
        float vo = sm[ty][tx];
        int s = s0 + tx;
        if (s < Ssz)
            vt[((long)(b * HEADS + h) * 32 + ty) * Ssz + s] = __float2bfloat16(vo);
        float sum = (s < Ssz) ? vo : 0.f;
        #pragma unroll
        for (int off = 16; off; off >>= 1) sum += __shfl_xor_sync(0xffffffffu, sum, off);
        if (tx == 0) atomicAdd(&vsum[(b * HEADS + h) * 32 + ty], sum);
    }

    float v = sm[tx][ty];
    if (part < 2) {
        float sq = v * v;
        #pragma unroll
        for (int off = 16; off; off >>= 1) sq += __shfl_xor_sync(0xffffffffu, sq, off);
        float n = sqrtf(sq);
        v = v / fmaxf(n, 1e-12f);
    }
    int s = s0 + ty;

    if (doAux) {
        if (part == 0) {
            float vq = v * SC;
            float vhi = __shfl_down_sync(0xffffffffu, vq, 1);
            if ((tx & 1) == 0 && s < Ssz)
                qb[((long)(b * HEADS + h) * SL + s) * 16 + (tx >> 1)] = pack_bf16x2(vq, vhi);
        } else if (part == 1) {
            float vhi = __shfl_down_sync(0xffffffffu, v, 1);
            if ((tx & 1) == 0 && s < Ssz)
                kb[((long)(b * HEADS + h) * SL + s) * 16 + (tx >> 1)] = pack_bf16x2(v, vhi);
        }
    } else {
        if (s < Ssz)
            qkvt[(((long)(b * 3 + part) * 8 + h) * Ssz + s) * 32 + tx] = v;
    }
}

// ---------------- mma.sync bf16 flash attention (local branch) ----------------
__global__ void __launch_bounds__(128, 4)
attn_tc_kernel(const u32* __restrict__ qb, const u32* __restrict__ kb,
               const __nv_bfloat16* __restrict__ vt,
               const float* __restrict__ vsum, float* __restrict__ out)
{
    __shared__ u32 Ks[64][36];
    __shared__ u32 Vs[32][36];
    const int tid = threadIdx.x;
    const int w = tid >> 5, lane = tid & 31;
    const int g = lane >> 2, t = lane & 3;
    const int bh = blockIdx.x;
    const int b = bh >> 3, h = bh & 7;
    const int q0 = blockIdx.y * 128;
    const u32* Qb = qb + (long)bh * SL * 16;
    const u32* Kb = kb + (long)bh * SL * 16;
    const char* Vg = (const char*)(vt + (long)bh * 32 * SL);

    u32 qa[2][2][4];
    #pragma unroll
    for (int m = 0; m < 2; m++) {
        long r0 = q0 + w * 32 + m * 16 + g;
        #pragma unroll
        for (int kt = 0; kt < 2; kt++) {
            int cp = kt * 8 + t;
            qa[m][kt][0] = Qb[r0 * 16 + cp];
            qa[m][kt][1] = Qb[(r0 + 8) * 16 + cp];
            qa[m][kt][2] = Qb[r0 * 16 + cp + 4];
            qa[m][kt][3] = Qb[(r0 + 8) * 16 + cp + 4];
        }
    }

    float oacc[2][4][4];
    #pragma unroll
    for (int m = 0; m < 2; m++)
        #pragma unroll
        for (int j = 0; j < 4; j++)
            #pragma unroll
            for (int i = 0; i < 4; i++) oacc[m][j][i] = 0.f;
    float lrow[2][2] = {{0.f, 0.f}, {0.f, 0.f}};

    for (int blk = 0; blk < 36; blk++) {
        const int k0 = blk * 64;
        {
            int r = tid >> 1, hf = (tid & 1) * 8;
            const uint4* kp = (const uint4*)(Kb + ((long)(k0 + r) * 16 + hf));
            uint4 k0v = kp[0], k1v = kp[1];
            u32* kd = &Ks[r][hf];
            kd[0] = k0v.x; kd[1] = k0v.y; kd[2] = k0v.z; kd[3] = k0v.w;
            kd[4] = k1v.x; kd[5] = k1v.y; kd[6] = k1v.z; kd[7] = k1v.w;
        }
        {
            int r = tid >> 2, s4 = tid & 3;
            const uint4* vr = (const uint4*)(Vg + (long)r * (SL * 2) + k0 * 2 + s4 * 32);
            uint4 v0 = vr[0], v1 = vr[1];
            u32* vd = &Vs[r][s4 * 8];
            vd[0] = v0.x; vd[1] = v0.y; vd[2] = v0.z; vd[3] = v0.w;
            vd[4] = v1.x; vd[5] = v1.y; vd[6] = v1.z; vd[7] = v1.w;
        }
        __syncthreads();

        #pragma unroll
        for (int hf = 0; hf < 2; hf++) {
            float sacc[2][4][4];
            #pragma unroll
            for (int m = 0; m < 2; m++)
                #pragma unroll
                for (int j = 0; j < 4; j++)
                    #pragma unroll
                    for (int i = 0; i < 4; i++) sacc[m][j][i] = 0.f;

            #pragma unroll
            for (int kt = 0; kt < 2; kt++)
                #pragma unroll
                for (int j = 0; j < 4; j++) {
                    int jj = hf * 4 + j;
                    u32 bb[2] = { Ks[8 * jj + g][kt * 8 + t], Ks[8 * jj + g][kt * 8 + t + 4] };
                    mma16816(sacc[0][j], qa[0][kt], bb);
                    mma16816(sacc[1][j], qa[1][kt], bb);
                }

            u32 fa[2][2][4];
            #pragma unroll
            for (int m = 0; m < 2; m++)
                #pragma unroll
                for (int j = 0; j < 4; j++) {
                    float p0 = __expf(sacc[m][j][0]);
                    float p1 = __expf(sacc[m][j][1]);
                    float p2 = __expf(sacc[m][j][2]);
                    float p3 = __expf(sacc[m][j][3]);
                    lrow[m][0] += p0 + p1;
                    lrow[m][1] += p2 + p3;
                    int kkl = j >> 1, hi2 = (j & 1) * 2;
                    fa[m][kkl][hi2 + 0] = pack_bf16x2(p0 - 1.f, p1 - 1.f);
                    fa[m][kkl][hi2 + 1] = pack_bf16x2(p2 - 1.f, p3 - 1.f);
                }

            #pragma unroll
            for (int kkl = 0; kkl < 2; kkl++) {
                int kk = hf * 2 + kkl;
                #pragma unroll
                for (int jn = 0; jn < 4; jn++) {
                    u32 bb[2] = { Vs[8 * jn + g][kk * 8 + t], Vs[8 * jn + g][kk * 8 + t + 4] };
                    mma16816(oacc[0][jn], fa[0][kkl], bb);
                    mma16816(oacc[1][jn], fa[1][kkl], bb);
                }
            }
        }
        __syncthreads();
    }

    #pragma unroll
    for (int m = 0; m < 2; m++)
        #pragma unroll
        for (int rh = 0; rh < 2; rh++) {
            float l = lrow[m][rh];
            l += __shfl_xor_sync(0xffffffffu, l, 1);
            l += __shfl_xor_sync(0xffffffffu, l, 2);
            lrow[m][rh] = l;
        }

    const float* vs = vsum + bh * 32;
    long ob = (long)b * CC + h * HD;
    #pragma unroll
    for (int m = 0; m < 2; m++)
        #pragma unroll
        for (int rh = 0; rh < 2; rh++) {
            float inv = 1.f / lrow[m][rh];
            int row = q0 + w * 32 + m * 16 + g + rh * 8;
            #pragma unroll
            for (int jn = 0; jn < 4; jn++) {
                int d = 8 * jn + 2 * t;
                float v0 = (__ldg(vs + d)     + oacc[m][jn][rh * 2 + 0]) * inv;
                float v1 = (__ldg(vs + d + 1) + oacc[m][jn][rh * 2 + 1]) * inv;
                out[(ob + d)     * (long)SL + row] = v0;
                out[(ob + d + 1) * (long)SL + row] = v1;
            }
        }
}

// ---------------- SIMT flash attention (global branch, S=144) ----------------
__global__ void __launch_bounds__(128, 2)
attn_kernel(const float* __restrict__ qkvt, float* __restrict__ out, int Ssz)
{
    __shared__ __align__(16) float ks[64][32];
    __shared__ __align__(16) float vs[64][32];
    const int bh = blockIdx.x;
    const int b = bh >> 3, h = bh & 7;
    const long base = ((long)(b * 3) * HEADS + h) * Ssz * HD;
    const float* Q = qkvt + base;
    const float* K = Q + (long)HEADS * Ssz * HD;
    const float* V = Q + 2L * HEADS * Ssz * HD;
    const int tid = threadIdx.x;
    const int rowa = blockIdx.y * 256 + tid;
    const int rowb = rowa + 128;
    const bool va = rowa < Ssz;
    const bool vb = rowb < Ssz;

    const u64 sc2 = pack2(SC, SC);

    u64 qa[16], qb2[16];
    #pragma unroll
    for (int i = 0; i < 16; i++) { qa[i] = 0ULL; qb2[i] = 0ULL; }
    if (va) {
        #pragma unroll
        for (int i = 0; i < 8; i++) {
            u64 t0, t1;
            lds2(Q + (long)rowa * 32 + i * 4, t0, t1);
            qa[2 * i] = ffma2(t0, sc2, 0ULL);
            qa[2 * i + 1] = ffma2(t1, sc2, 0ULL);
        }
    }
    if (vb) {
        #pragma unroll
        for (int i = 0; i < 8; i++) {
            u64 t0, t1;
            lds2(Q + (long)rowb * 32 + i * 4, t0, t1);
            qb2[2 * i] = ffma2(t0, sc2, 0ULL);
            qb2[2 * i + 1] = ffma2(t1, sc2, 0ULL);
        }
    }

    u64 aa[16], ab[16];
    #pragma unroll
    for (int i = 0; i < 16; i++) { aa[i] = 0ULL; ab[i] = 0ULL; }
    float la = 0.f, lb = 0.f;

    for (int j0 = 0; j0 < Ssz; j0 += 64) {
        int cnt = min(64, Ssz - j0);
        int nf4 = cnt * 8;
        const float4* kp = (const float4*)(K + (long)j0 * 32);
        const float4* vp = (const float4*)(V + (long)j0 * 32);
        #pragma unroll
        for (int t = 0; t < 4; t++) {
            int i = tid + t * 128;
            if (i < nf4) { ((float4*)ks)[i] = kp[i]; ((float4*)vs)[i] = vp[i]; }
        }
        __syncthreads();
        for (int j = 0; j < cnt; j++) {
            u64 kt[16];
            #pragma unroll
            for (int i = 0; i < 8; i++) lds2(&ks[j][i * 4], kt[2 * i], kt[2 * i + 1]);
            u64 da0 = 0ULL, da1 = 0ULL, db0 = 0ULL, db1 = 0ULL;
            #pragma unroll
            for (int i = 0; i < 16; i += 2) {
                da0 = ffma2(qa[i], kt[i], da0);
                da1 = ffma2(qa[i + 1], kt[i + 1], da1);
                db0 = ffma2(qb2[i], kt[i], db0);
                db1 = ffma2(qb2[i + 1], kt[i + 1], db1);
            }
            float2 ea0 = unpack2(da0), ea1 = unpack2(da1);
            float2 eb0 = unpack2(db0), eb1 = unpack2(db1);
            float pa = __expf((ea0.x + ea0.y) + (ea1.x + ea1.y));
            float pb = __expf((eb0.x + eb0.y) + (eb1.x + eb1.y));
            la += pa; lb += pb;
            u64 pa2 = pack2(pa, pa);
            u64 pb2 = pack2(pb, pb);
            u64 vt2[16];
            #pragma unroll
            for (int i = 0; i < 8; i++) lds2(&vs[j][i * 4], vt2[2 * i], vt2[2 * i + 1]);
            #pragma unroll
            for (int i = 0; i < 16; i++) {
                aa[i] = ffma2(pa2, vt2[i], aa[i]);
                ab[i] = ffma2(pb2, vt2[i], ab[i]);
            }
        }
        __syncthreads();
    }

    long ob = (long)b * CC + h * HD;
    if (va) {
        float inv = 1.f / la;
        #pragma unroll
        for (int i = 0; i < 16; i++) {
            float2 t = unpack2(aa[i]);
            out[(ob + 2 * i) * (long)Ssz + rowa] = t.x * inv;
            out[(ob + 2 * i + 1) * (long)Ssz + rowa] = t.y * inv;
        }
    }
    if (vb) {
        float inv = 1.f / lb;
        #pragma unroll
        for (int i = 0; i < 16; i++) {
            float2 t = unpack2(ab[i]);
            out[(ob + 2 * i) * (long)Ssz + rowb] = t.x * inv;
            out[(ob + 2 * i + 1) * (long)Ssz + rowb] = t.y * inv;
        }
    }
}

// ---------------- 4x4 average pool ----------------
__global__ void avgpool_kernel(const float* __restrict__ x, float* __restrict__ xc)
{
    int idx = blockIdx.x * blockDim.x + threadIdx.x;
    if (idx >= BB * CC * SG) return;
    int p = idx % SG;
    int c = (idx / SG) % CC;
    int b = idx / (SG * CC);
    int i = p / 12, j = p % 12;
    const float* xp = x + ((long)b * CC + c) * SL;
    float s = 0.f;
    #pragma unroll
    for (int dy = 0; dy < 4; dy++)
        #pragma unroll
        for (int dx = 0; dx < 4; dx++)
            s += xp[(i * 4 + dy) * 48 + j * 4 + dx];
    xc[idx] = s * (1.f / 16.f);
}

// ---------------- bilinear upsample into concat ch 256..511 ----------------
__global__ void upsample_kernel(const float* __restrict__ g, float* __restrict__ concat)
{
    int idx = blockIdx.x * blockDim.x + threadIdx.x;
    if (idx >= BB * CC * SL) return;
    int p = idx % SL;
    int c = (idx / SL) % CC;
    int b = idx / (SL * CC);
    int y = p / 48, x = p % 48;
    float fy = (y + 0.5f) * 0.25f - 0.5f;
    float fx = (x + 0.5f) * 0.25f - 0.5f;
    int y0 = (int)floorf(fy), x0 = (int)floorf(fx);
    float wy = fy - y0, wx = fx - x0;
    int ya = min(11, max(0, y0)), yb = min(11, max(0, y0 + 1));
    int xa = min(11, max(0, x0)), xb = min(11, max(0, x0 + 1));
    const float* gp = g + ((long)b * CC + c) * SG;
    float v00 = gp[ya * 12 + xa], v01 = gp[ya * 12 + xb];
    float v10 = gp[yb * 12 + xa], v11 = gp[yb * 12 + xb];
    float v = (1.f - wy) * ((1.f - wx) * v00 + wx * v01)
            +        wy  * ((1.f - wx) * v10 + wx * v11);
    concat[((long)b * 512 + 256 + c) * SL + p] = v;
}

// ---------------- launch ----------------
extern "C" void kernel_launch(void* const* d_in, const int* in_sizes, int n_in,
                              void* d_out, int out_size)
{
    const float* x        = (const float*)d_in[0];
    const float* w_qkv_l  = (const float*)d_in[1];
    const float* w_proj_l = (const float*)d_in[2];
    const float* b_proj_l = (const float*)d_in[3];
    const float* w_qkv_g  = (const float*)d_in[4];
    const float* w_proj_g = (const float*)d_in[5];
    const float* b_proj_g = (const float*)d_in[6];
    const float* w_f1     = (const float*)d_in[7];
    const float* b_f1     = (const float*)d_in[8];
    const float* w_f2     = (const float*)d_in[9];
    const float* b_f2     = (const float*)d_in[10];
    float* out = (float*)d_out;

    float *qkv, *attn, *concat, *hbuf, *xc, *qkvg, *qkvtg, *attng, *gg, *vsum;
    __nv_bfloat16* vt;
    u32 *wh, *wl, *kb, *qb;
    cudaGetSymbolAddress((void**)&qkv,    g_qkv);
    cudaGetSymbolAddress((void**)&attn,   g_attn);
    cudaGetSymbolAddress((void**)&concat, g_concat);
    cudaGetSymbolAddress((void**)&hbuf,   g_h);
    cudaGetSymbolAddress((void**)&xc,     g_xc);
    cudaGetSymbolAddress((void**)&qkvg,   g_qkvg);
    cudaGetSymbolAddress((void**)&qkvtg,  g_qkvtg);
    cudaGetSymbolAddress((void**)&attng,  g_attng);
    cudaGetSymbolAddress((void**)&gg,     g_g);
    cudaGetSymbolAddress((void**)&vt,     g_vt);
    cudaGetSymbolAddress((void**)&vsum,   g_vsum);
    cudaGetSymbolAddress((void**)&wh,     g_wh);
    cudaGetSymbolAddress((void**)&wl,     g_wl);
    cudaGetSymbolAddress((void**)&kb,     g_kb);
    cudaGetSymbolAddress((void**)&qb,     g_qb);

    // one-time stream/event setup (first call is the uncaptured correctness run)
    static cudaStream_t s2 = nullptr;
    static cudaEvent_t evF = nullptr, evJ = nullptr;
    if (!s2) {
        cudaStreamCreateWithFlags(&s2, cudaStreamNonBlocking);
        cudaEventCreateWithFlags(&evF, cudaEventDisableTiming);
        cudaEventCreateWithFlags(&evJ, cudaEventDisableTiming);
    }

    dim3 blk(16, 16);

    // fork: global branch runs on s2, concurrent with local branch on stream 0
    cudaEventRecord(evF, 0);
    cudaStreamWaitEvent(s2, evF, 0);

    // ---- global branch (s2) ----
    avgpool_kernel<<<(BB * CC * SG + 255) / 256, 256, 0, s2>>>(x, xc);
    gemm_kernel<128><<<dim3((SG + 63) / 64, 768 / 128, BB), blk, 0, s2>>>(xc, w_qkv_g, nullptr, qkvg,
                                                                          256, SG, 256L * SG, 768L * SG, 0);
    tnorm_kernel<<<dim3((SG + 31) / 32, BB * 24), dim3(32, 32), 0, s2>>>(qkvg, qkvtg, SG, vt, vsum, kb, qb, 0);
    attn_kernel<<<dim3(BB * HEADS, (SG + 255) / 256), 128, 0, s2>>>(qkvtg, attng, SG);
    gemm_kernel<128><<<dim3((SG + 63) / 64, 256 / 128, BB), blk, 0, s2>>>(attng, w_proj_g, b_proj_g, gg,
                                                                          256, SG, 256L * SG, 256L * SG, 0);
    upsample_kernel<<<(BB * CC * SL + 255) / 256, 256, 0, s2>>>(gg, concat);
    cudaEventRecord(evJ, s2);

    // ---- local branch (stream 0) ----
    cudaMemsetAsync(vsum, 0, BB * HEADS * 32 * sizeof(float), 0);
    wsplit_all_kernel<<<(WTOT + 255) / 256, 256>>>(w_qkv_l, w_proj_l, w_f1, w_f2, wh, wl);
    gemm_tc_kernel<0><<<dim3(SL / 128, 768 / 128, BB), 256>>>(x, wh + WOFF_QKV, wl + WOFF_QKV,
                                                              nullptr, qkv, 256, SL, 256L * SL, 768L * SL);
    tnorm_kernel<<<dim3(SL / 32, BB * 24), dim3(32, 32)>>>(qkv, nullptr, SL, vt, vsum, kb, qb, 1);
    attn_tc_kernel<<<dim3(BB * HEADS, SL / 128), 128>>>(qb, kb, vt, vsum, attn);
    gemm_tc_kernel<0><<<dim3(SL / 128, 256 / 128, BB), 256>>>(attn, wh + WOFF_PROJ, wl + WOFF_PROJ,
                                                              b_proj_l, concat, 256, SL, 256L * SL, 512L * SL);

    // join: f1 needs both halves of concat
    cudaStreamWaitEvent(0, evJ, 0);

    gemm_tc_kernel<1><<<dim3(SL / 128, 256 / 128, BB), 256>>>(concat, wh + WOFF_F1, wl + WOFF_F1,
                                                              b_f1, hbuf, 512, SL, 512L * SL, 256L * SL);
    gemm_tc_kernel<0><<<dim3(SL / 128, 256 / 128, BB), 256>>>(hbuf, wh + WOFF_F2, wl + WOFF_F2,
                                                              b_f2, out, 256, SL, 256L * SL, 256L * SL);
}

// round 17
// speedup vs baseline: 1.6000x; 1.0297x over previous
#include <cuda_runtime.h>
#include <cuda_bf16.h>
#include <math.h>

#define BB    4
#define CC    256
#define SL    2304     // 48*48
#define SG    144      // 12*12
#define HEADS 8
#define HD    32
#define SC    0.17677669529663687f

typedef unsigned long long u64;
typedef unsigned int u32;

// ---------------- helpers ----------------
__device__ __forceinline__ u64 ffma2(u64 a, u64 b, u64 c) {
    u64 d;
    asm("fma.rn.f32x2 %0, %1, %2, %3;" : "=l"(d) : "l"(a), "l"(b), "l"(c));
    return d;
}
__device__ __forceinline__ u64 pack2(float x, float y) {
    u64 d;
    asm("mov.b64 %0, {%1, %2};" : "=l"(d) : "f"(x), "f"(y));
    return d;
}
__device__ __forceinline__ float2 unpack2(u64 v) {
    float2 r;
    asm("mov.b64 {%0, %1}, %2;" : "=f"(r.x), "=f"(r.y) : "l"(v));
    return r;
}
__device__ __forceinline__ void lds2(const float* p, u64& a, u64& b) {
    double2 t = *(const double2*)p;
    a = (u64)__double_as_longlong(t.x);
    b = (u64)__double_as_longlong(t.y);
}
__device__ __forceinline__ u32 pack_bf16x2(float lo, float hi) {
    u32 r;
    asm("cvt.rn.bf16x2.f32 %0, %1, %2;" : "=r"(r) : "f"(hi), "f"(lo));
    return r;
}
__device__ __forceinline__ u32 bf16_bits(float x) {
    u32 r;
    asm("cvt.rn.bf16x2.f32 %0, %1, %2;" : "=r"(r) : "f"(0.f), "f"(x));
    return r & 0xFFFFu;
}
__device__ __forceinline__ void split2(float x, float y, u32& hi, u32& lo) {
    u32 hx = bf16_bits(x), hy = bf16_bits(y);
    hi = hx | (hy << 16);
    float fx = __uint_as_float(hx << 16);
    float fy = __uint_as_float(hy << 16);
    lo = pack_bf16x2(x - fx, y - fy);
}
__device__ __forceinline__ void mma16816(float* c, const u32* a, const u32* b) {
    asm volatile("mma.sync.aligned.m16n8k16.row.col.f32.bf16.bf16.f32 "
        "{%0,%1,%2,%3}, {%4,%5,%6,%7}, {%8,%9}, {%0,%1,%2,%3};"
        : "+f"(c[0]), "+f"(c[1]), "+f"(c[2]), "+f"(c[3])
        : "r"(a[0]), "r"(a[1]), "r"(a[2]), "r"(a[3]), "r"(b[0]), "r"(b[1]));
}
// expm1 on |x| <= 0.177 via 4th-order Taylor: err <= x^5/120 ~ 1.4e-6
__device__ __forceinline__ float expm1_poly(float x) {
    float t = fmaf(x, 1.f / 24.f, 1.f / 6.f);
    t = fmaf(x, t, 0.5f);
    return fmaf(x * x, t, x);
}

// ---------------- scratch ----------------
__device__ float g_qkv   [BB*768*SL];
__device__ float g_attn  [BB*CC*SL];
__device__ float g_concat[(long)BB*512*SL];
__device__ float g_h     [BB*CC*SL];
__device__ float g_xc    [BB*CC*SG];
__device__ float g_qkvg  [BB*768*SG];
__device__ float g_qkvtg [BB*768*SG];
__device__ float g_attng [BB*CC*SG];
__device__ float g_g     [BB*CC*SG];
__device__ __nv_bfloat16 g_vt[BB*HEADS*32*SL];
__device__ u32 g_kb[BB*HEADS*SL*16];
__device__ u32 g_qb[BB*HEADS*SL*16];
__device__ float g_vsum[BB*HEADS*32];
#define WOFF_QKV  0
#define WOFF_PROJ 98304
#define WOFF_F1   131072
#define WOFF_F2   196608
#define WTOT      229376
__device__ u32 g_wh[WTOT];
__device__ u32 g_wl[WTOT];

// ---------------- combined weight split ----------------
__global__ void wsplit_all_kernel(const float* __restrict__ Wq, const float* __restrict__ Wp,
                                  const float* __restrict__ Wf1, const float* __restrict__ Wf2,
                                  u32* __restrict__ Wh, u32* __restrict__ Wl)
{
    int i = blockIdx.x * blockDim.x + threadIdx.x;
    if (i >= WTOT) return;
    const float* src;
    int off;
    if (i < WOFF_PROJ)      { src = Wq;  off = i - WOFF_QKV; }
    else if (i < WOFF_F1)   { src = Wp;  off = i - WOFF_PROJ; }
    else if (i < WOFF_F2)   { src = Wf1; off = i - WOFF_F1; }
    else                    { src = Wf2; off = i - WOFF_F2; }
    float x = src[2 * off], y = src[2 * off + 1];
    u32 h, l;
    split2(x, y, h, l);
    Wh[i] = h; Wl[i] = l;
}

// ---------------- TC conv1x1 GEMM: 128o x 128s tile, 256 threads, prefetch ----------------
template<int GELU>
__global__ void __launch_bounds__(256, 2)
gemm_tc_kernel(const float* __restrict__ X, const u32* __restrict__ Wh,
               const u32* __restrict__ Wl, const float* __restrict__ bias,
               float* __restrict__ Y, int Cin, int Ssz, long xBS, long yBS)
{
    __shared__ u32 sWh[128][12], sWl[128][12];
    __shared__ u32 sXh[128][12], sXl[128][12];
    const int tid = threadIdx.x;
    const int w = tid >> 5, lane = tid & 31;
    const int g = lane >> 2, t = lane & 3;
    const int ow = w >> 2, sq = w & 3;
    const int s0 = blockIdx.x * 128;
    const int o0 = blockIdx.y * 128;
    const int b  = blockIdx.z;
    const float* Xb = X + (long)b * xBS;
    const int cp = Cin >> 1;

    const int wrow = tid >> 1, whf = (tid & 1) * 4;
    const int xsr = tid & 127, xcg = tid >> 7;

    float acc[4][4][4];
    #pragma unroll
    for (int m = 0; m < 4; m++)
        #pragma unroll
        for (int n = 0; n < 4; n++)
            #pragma unroll
            for (int i = 0; i < 4; i++) acc[m][n][i] = 0.f;

    uint4 pwh, pwl;
    float px[8];
    {
        pwh = *(const uint4*)(Wh + (long)(o0 + wrow) * cp + whf);
        pwl = *(const uint4*)(Wl + (long)(o0 + wrow) * cp + whf);
        const float* xb0 = Xb + (long)(xcg * 8) * Ssz + s0 + xsr;
        #pragma unroll
        for (int j = 0; j < 8; j++) px[j] = xb0[(long)j * Ssz];
    }

    for (int c0 = 0; c0 < Cin; c0 += 16) {
        *(uint4*)&sWh[wrow][whf] = pwh;
        *(uint4*)&sWl[wrow][whf] = pwl;
        #pragma unroll
        for (int j = 0; j < 4; j++) {
            u32 h, l;
            split2(px[2 * j], px[2 * j + 1], h, l);
            sXh[xsr][xcg * 4 + j] = h;
            sXl[xsr][xcg * 4 + j] = l;
        }
        __syncthreads();

        if (c0 + 16 < Cin) {
            int cn = c0 + 16;
            pwh = *(const uint4*)(Wh + (long)(o0 + wrow) * cp + (cn >> 1) + whf);
            pwl = *(const uint4*)(Wl + (long)(o0 + wrow) * cp + (cn >> 1) + whf);
            const float* xb0 = Xb + (long)(cn + xcg * 8) * Ssz + s0 + xsr;
            #pragma unroll
            for (int j = 0; j < 8; j++) px[j] = xb0[(long)j * Ssz];
        }

        #pragma unroll
        for (int m = 0; m < 4; m++) {
            int ro = ow * 64 + m * 16;
            u32 ah[4], al[4];
            ah[0] = sWh[ro + g][t];         al[0] = sWl[ro + g][t];
            ah[1] = sWh[ro + g + 8][t];     al[1] = sWl[ro + g + 8][t];
            ah[2] = sWh[ro + g][t + 4];     al[2] = sWl[ro + g][t + 4];
            ah[3] = sWh[ro + g + 8][t + 4]; al[3] = sWl[ro + g + 8][t + 4];
            #pragma unroll
            for (int n = 0; n < 4; n++) {
                int xr = sq * 32 + n * 8 + g;
                u32 bh[2] = { sXh[xr][t], sXh[xr][t + 4] };
                u32 bl[2] = { sXl[xr][t], sXl[xr][t + 4] };
                mma16816(acc[m][n], ah, bh);
                mma16816(acc[m][n], al, bh);
                mma16816(acc[m][n], ah, bl);
            }
        }
        __syncthreads();
    }

    #pragma unroll
    for (int m = 0; m < 4; m++) {
        int o = o0 + ow * 64 + m * 16 + g;
        float bv0 = bias ? bias[o] : 0.f;
        float bv1 = bias ? bias[o + 8] : 0.f;
        long base0 = (long)b * yBS + (long)o * Ssz;
        long base1 = base0 + 8L * Ssz;
        #pragma unroll
        for (int n = 0; n < 4; n++) {
            int s = s0 + sq * 32 + n * 8 + 2 * t;
            float y00 = acc[m][n][0] + bv0, y01 = acc[m][n][1] + bv0;
            float y10 = acc[m][n][2] + bv1, y11 = acc[m][n][3] + bv1;
            if (GELU) {
                y00 = 0.5f * y00 * (1.f + erff(y00 * 0.70710678118654752f));
                y01 = 0.5f * y01 * (1.f + erff(y01 * 0.70710678118654752f));
                y10 = 0.5f * y10 * (1.f + erff(y10 * 0.70710678118654752f));
                y11 = 0.5f * y11 * (1.f + erff(y11 * 0.70710678118654752f));
            }
            *(float2*)&Y[base0 + s] = make_float2(y00, y01);
            *(float2*)&Y[base1 + s] = make_float2(y10, y11);
        }
    }
}

// ---------------- SIMT conv1x1 GEMM (global branch only) ----------------
template<int BM>
__global__ void __launch_bounds__(256)
gemm_kernel(const float* __restrict__ X, const float* __restrict__ Wm,
            const float* __restrict__ bias, float* __restrict__ Y,
            int Cin, int Ssz, long xBS, long yBS, int doGelu)
{
    constexpr int MR = BM / 16;
    constexpr int TPO = 16 / MR;
    __shared__ __align__(16) float Ws[16][BM];
    __shared__ __align__(16) float Xs[16][64];
    const int tx = threadIdx.x, ty = threadIdx.y;
    const int tid = ty * 16 + tx;
    const int s0 = blockIdx.x * 64;
    const int o0 = blockIdx.y * BM;
    const int b  = blockIdx.z;
    const float* Xb = X + (long)b * xBS;
    const bool full = (s0 + 64 <= Ssz);

    const int lw_o = tid / TPO;
    const int lw_c = (tid % TPO) * MR;
    const int lx_c = tid >> 4;
    const int lx_s = (tid & 15) * 4;

    u64 acc[MR][2];
    #pragma unroll
    for (int i = 0; i < MR; i++) { acc[i][0] = 0ULL; acc[i][1] = 0ULL; }

    for (int c0 = 0; c0 < Cin; c0 += 16) {
        {
            const float* wrow = Wm + (long)(o0 + lw_o) * Cin + c0 + lw_c;
            #pragma unroll
            for (int r = 0; r < MR; r += 4) {
                float4 w = *(const float4*)(wrow + r);
                Ws[lw_c + r + 0][lw_o] = w.x; Ws[lw_c + r + 1][lw_o] = w.y;
                Ws[lw_c + r + 2][lw_o] = w.z; Ws[lw_c + r + 3][lw_o] = w.w;
            }
        }
        {
            const float* xrow = Xb + (long)(c0 + lx_c) * Ssz + s0 + lx_s;
            if (full) {
                float4 xv = *(const float4*)xrow;
                Xs[lx_c][lx_s + 0] = xv.x; Xs[lx_c][lx_s + 1] = xv.y;
                Xs[lx_c][lx_s + 2] = xv.z; Xs[lx_c][lx_s + 3] = xv.w;
            } else {
                #pragma unroll
                for (int i = 0; i < 4; i++)
                    Xs[lx_c][lx_s + i] = (s0 + lx_s + i < Ssz) ? xrow[i] : 0.f;
            }
        }
        __syncthreads();

        #pragma unroll
        for (int c = 0; c < 16; c++) {
            u64 x01, x23;
            lds2(&Xs[c][tx * 4], x01, x23);
            #pragma unroll
            for (int r = 0; r < MR; r += 4) {
                float4 a = *(const float4*)&Ws[c][ty * MR + r];
                u64 p;
                p = pack2(a.x, a.x); acc[r+0][0] = ffma2(p, x01, acc[r+0][0]); acc[r+0][1] = ffma2(p, x23, acc[r+0][1]);
                p = pack2(a.y, a.y); acc[r+1][0] = ffma2(p, x01, acc[r+1][0]); acc[r+1][1] = ffma2(p, x23, acc[r+1][1]);
                p = pack2(a.z, a.z); acc[r+2][0] = ffma2(p, x01, acc[r+2][0]); acc[r+2][1] = ffma2(p, x23, acc[r+2][1]);
                p = pack2(a.w, a.w); acc[r+3][0] = ffma2(p, x01, acc[r+3][0]); acc[r+3][1] = ffma2(p, x23, acc[r+3][1]);
            }
        }
        __syncthreads();
    }

    #pragma unroll
    for (int i = 0; i < MR; i++) {
        int o = o0 + ty * MR + i;
        float bv = bias ? bias[o] : 0.f;
        float2 p0 = unpack2(acc[i][0]);
        float2 p1 = unpack2(acc[i][1]);
        float vals[4] = {p0.x, p0.y, p1.x, p1.y};
        #pragma unroll
        for (int j = 0; j < 4; j++) {
            int s = s0 + tx * 4 + j;
            if (s < Ssz) {
                float v = vals[j] + bv;
                if (doGelu) v = 0.5f * v * (1.f + erff(v * 0.70710678118654752f));
                Y[(long)b * yBS + (long)o * Ssz + s] = v;
            }
        }
    }
}

// ---- tnorm: local branch -> qb/kb/vt/vsum (bf16 only); global -> fp32 qkvt ----
__global__ void tnorm_kernel(const float* __restrict__ qkv, float* __restrict__ qkvt, int Ssz,
                             __nv_bfloat16* __restrict__ vt, float* __restrict__ vsum,
                             u32* __restrict__ kb, u32* __restrict__ qb, int doAux)
{
    __shared__ float sm[32][33];
    const int bp = blockIdx.y;
    const int b = bp / 24;
    const int rem = bp % 24;
    const int part = rem / 8;
    const int h = rem % 8;
    const int s0 = blockIdx.x * 32;
    const int tx = threadIdx.x, ty = threadIdx.y;

    {
        int s = s0 + tx;
        float v = 0.f;
        if (s < Ssz) v = qkv[((long)b * 768 + part * 256 + h * 32 + ty) * Ssz + s];
        sm[ty][tx] = v;
    }
    __syncthreads();

    if (doAux && part == 2) {
        float vo = sm[ty][tx];
        int s = s0 + tx;
        if (s < Ssz)
            vt[((long)(b * HEADS + h) * 32 + ty) * Ssz + s] = __float2bfloat16(vo);
        float sum = (s < Ssz) ? vo : 0.f;
        #pragma unroll
        for (int off = 16; off; off >>= 1) sum += __shfl_xor_sync(0xffffffffu, sum, off);
        if (tx == 0) atomicAdd(&vsum[(b * HEADS + h) * 32 + ty], sum);
    }

    float v = sm[tx][ty];
    if (part < 2) {
        float sq = v * v;
        #pragma unroll
        for (int off = 16; off; off >>= 1) sq += __shfl_xor_sync(0xffffffffu, sq, off);
        float n = sqrtf(sq);
        v = v / fmaxf(n, 1e-12f);
    }
    int s = s0 + ty;

    if (doAux) {
        if (part == 0) {
            float vq = v * SC;
            float vhi = __shfl_down_sync(0xffffffffu, vq, 1);
            if ((tx & 1) == 0 && s < Ssz)
                qb[((long)(b * HEADS + h) * SL + s) * 16 + (tx >> 1)] = pack_bf16x2(vq, vhi);
        } else if (part == 1) {
            float vhi = __shfl_down_sync(0xffffffffu, v, 1);
            if ((tx & 1) == 0 && s < Ssz)
                kb[((long)(b * HEADS + h) * SL + s) * 16 + (tx >> 1)] = pack_bf16x2(v, vhi);
        }
    } else {
        if (s < Ssz)
            qkvt[(((long)(b * 3 + part) * 8 + h) * Ssz + s) * 32 + tx] = v;
    }
}

// ---------------- mma.sync bf16 flash attention (local branch) ----------------
// exp via bounded-domain Taylor poly (no MUFU); l = SL + sum(F).
__global__ void __launch_bounds__(128, 4)
attn_tc_kernel(const u32* __restrict__ qb, const u32* __restrict__ kb,
               const __nv_bfloat16* __restrict__ vt,
               const float* __restrict__ vsum, float* __restrict__ out)
{
    __shared__ u32 Ks[64][36];
    __shared__ u32 Vs[32][36];
    const int tid = threadIdx.x;
    const int w = tid >> 5, lane = tid & 31;
    const int g = lane >> 2, t = lane & 3;
    const int bh = blockIdx.x;
    const int b = bh >> 3, h = bh & 7;
    const int q0 = blockIdx.y * 128;
    const u32* Qb = qb + (long)bh * SL * 16;
    const u32* Kb = kb + (long)bh * SL * 16;
    const char* Vg = (const char*)(vt + (long)bh * 32 * SL);

    u32 qa[2][2][4];
    #pragma unroll
    for (int m = 0; m < 2; m++) {
        long r0 = q0 + w * 32 + m * 16 + g;
        #pragma unroll
        for (int kt = 0; kt < 2; kt++) {
            int cp = kt * 8 + t;
            qa[m][kt][0] = Qb[r0 * 16 + cp];
            qa[m][kt][1] = Qb[(r0 + 8) * 16 + cp];
            qa[m][kt][2] = Qb[r0 * 16 + cp + 4];
            qa[m][kt][3] = Qb[(r0 + 8) * 16 + cp + 4];
        }
    }

    float oacc[2][4][4];
    #pragma unroll
    for (int m = 0; m < 2; m++)
        #pragma unroll
        for (int j = 0; j < 4; j++)
            #pragma unroll
            for (int i = 0; i < 4; i++) oacc[m][j][i] = 0.f;
    float lrow[2][2] = {{0.f, 0.f}, {0.f, 0.f}};  // accumulates sum of F

    for (int blk = 0; blk < 36; blk++) {
        const int k0 = blk * 64;
        {
            int r = tid >> 1, hf = (tid & 1) * 8;
            const uint4* kp = (const uint4*)(Kb + ((long)(k0 + r) * 16 + hf));
            uint4 k0v = kp[0], k1v = kp[1];
            u32* kd = &Ks[r][hf];
            kd[0] = k0v.x; kd[1] = k0v.y; kd[2] = k0v.z; kd[3] = k0v.w;
            kd[4] = k1v.x; kd[5] = k1v.y; kd[6] = k1v.z; kd[7] = k1v.w;
        }
        {
            int r = tid >> 2, s4 = tid & 3;
            const uint4* vr = (const uint4*)(Vg + (long)r * (SL * 2) + k0 * 2 + s4 * 32);
            uint4 v0 = vr[0], v1 = vr[1];
            u32* vd = &Vs[r][s4 * 8];
            vd[0] = v0.x; vd[1] = v0.y; vd[2] = v0.z; vd[3] = v0.w;
            vd[4] = v1.x; vd[5] = v1.y; vd[6] = v1.z; vd[7] = v1.w;
        }
        __syncthreads();

        #pragma unroll
        for (int hf = 0; hf < 2; hf++) {
            float sacc[2][4][4];
            #pragma unroll
            for (int m = 0; m < 2; m++)
                #pragma unroll
                for (int j = 0; j < 4; j++)
                    #pragma unroll
                    for (int i = 0; i < 4; i++) sacc[m][j][i] = 0.f;

            #pragma unroll
            for (int kt = 0; kt < 2; kt++)
                #pragma unroll
                for (int j = 0; j < 4; j++) {
                    int jj = hf * 4 + j;
                    u32 bb[2] = { Ks[8 * jj + g][kt * 8 + t], Ks[8 * jj + g][kt * 8 + t + 4] };
                    mma16816(sacc[0][j], qa[0][kt], bb);
                    mma16816(sacc[1][j], qa[1][kt], bb);
                }

            u32 fa[2][2][4];
            #pragma unroll
            for (int m = 0; m < 2; m++)
                #pragma unroll
                for (int j = 0; j < 4; j++) {
                    float F0 = expm1_poly(sacc[m][j][0]);
                    float F1 = expm1_poly(sacc[m][j][1]);
                    float F2 = expm1_poly(sacc[m][j][2]);
                    float F3 = expm1_poly(sacc[m][j][3]);
                    lrow[m][0] += F0 + F1;
                    lrow[m][1] += F2 + F3;
                    int kkl = j >> 1, hi2 = (j & 1) * 2;
                    fa[m][kkl][hi2 + 0] = pack_bf16x2(F0, F1);
                    fa[m][kkl][hi2 + 1] = pack_bf16x2(F2, F3);
                }

            #pragma unroll
            for (int kkl = 0; kkl < 2; kkl++) {
                int kk = hf * 2 + kkl;
                #pragma unroll
                for (int jn = 0; jn < 4; jn++) {
                    u32 bb[2] = { Vs[8 * jn + g][kk * 8 + t], Vs[8 * jn + g][kk * 8 + t + 4] };
                    mma16816(oacc[0][jn], fa[0][kkl], bb);
                    mma16816(oacc[1][jn], fa[1][kkl], bb);
                }
            }
        }
        __syncthreads();
    }

    #pragma unroll
    for (int m = 0; m < 2; m++)
        #pragma unroll
        for (int rh = 0; rh < 2; rh++) {
            float l = lrow[m][rh];
            l += __shfl_xor_sync(0xffffffffu, l, 1);
            l += __shfl_xor_sync(0xffffffffu, l, 2);
            lrow[m][rh] = l + (float)SL;   // l = sum p = SL + sum F
        }

    const float* vs = vsum + bh * 32;
    long ob = (long)b * CC + h * HD;
    #pragma unroll
    for (int m = 0; m < 2; m++)
        #pragma unroll
        for (int rh = 0; rh < 2; rh++) {
            float inv = 1.f / lrow[m][rh];
            int row = q0 + w * 32 + m * 16 + g + rh * 8;
            #pragma unroll
            for (int jn = 0; jn < 4; jn++) {
                int d = 8 * jn + 2 * t;
                float v0 = (__ldg(vs + d)     + oacc[m][jn][rh * 2 + 0]) * inv;
                float v1 = (__ldg(vs + d + 1) + oacc[m][jn][rh * 2 + 1]) * inv;
                out[(ob + d)     * (long)SL + row] = v0;
                out[(ob + d + 1) * (long)SL + row] = v1;
            }
        }
}

// ---------------- SIMT flash attention (global branch, S=144) ----------------
__global__ void __launch_bounds__(128, 2)
attn_kernel(const float* __restrict__ qkvt, float* __restrict__ out, int Ssz)
{
    __shared__ __align__(16) float ks[64][32];
    __shared__ __align__(16) float vs[64][32];
    const int bh = blockIdx.x;
    const int b = bh >> 3, h = bh & 7;
    const long base = ((long)(b * 3) * HEADS + h) * Ssz * HD;
    const float* Q = qkvt + base;
    const float* K = Q + (long)HEADS * Ssz * HD;
    const float* V = Q + 2L * HEADS * Ssz * HD;
    const int tid = threadIdx.x;
    const int rowa = blockIdx.y * 256 + tid;
    const int rowb = rowa + 128;
    const bool va = rowa < Ssz;
    const bool vb = rowb < Ssz;

    const u64 sc2 = pack2(SC, SC);

    u64 qa[16], qb2[16];
    #pragma unroll
    for (int i = 0; i < 16; i++) { qa[i] = 0ULL; qb2[i] = 0ULL; }
    if (va) {
        #pragma unroll
        for (int i = 0; i < 8; i++) {
            u64 t0, t1;
            lds2(Q + (long)rowa * 32 + i * 4, t0, t1);
            qa[2 * i] = ffma2(t0, sc2, 0ULL);
            qa[2 * i + 1] = ffma2(t1, sc2, 0ULL);
        }
    }
    if (vb) {
        #pragma unroll
        for (int i = 0; i < 8; i++) {
            u64 t0, t1;
            lds2(Q + (long)rowb * 32 + i * 4, t0, t1);
            qb2[2 * i] = ffma2(t0, sc2, 0ULL);
            qb2[2 * i + 1] = ffma2(t1, sc2, 0ULL);
        }
    }

    u64 aa[16], ab[16];
    #pragma unroll
    for (int i = 0; i < 16; i++) { aa[i] = 0ULL; ab[i] = 0ULL; }
    float la = 0.f, lb = 0.f;

    for (int j0 = 0; j0 < Ssz; j0 += 64) {
        int cnt = min(64, Ssz - j0);
        int nf4 = cnt * 8;
        const float4* kp = (const float4*)(K + (long)j0 * 32);
        const float4* vp = (const float4*)(V + (long)j0 * 32);
        #pragma unroll
        for (int t = 0; t < 4; t++) {
            int i = tid + t * 128;
            if (i < nf4) { ((float4*)ks)[i] = kp[i]; ((float4*)vs)[i] = vp[i]; }
        }
        __syncthreads();
        for (int j = 0; j < cnt; j++) {
            u64 kt[16];
            #pragma unroll
            for (int i = 0; i < 8; i++) lds2(&ks[j][i * 4], kt[2 * i], kt[2 * i + 1]);
            u64 da0 = 0ULL, da1 = 0ULL, db0 = 0ULL, db1 = 0ULL;
            #pragma unroll
            for (int i = 0; i < 16; i += 2) {
                da0 = ffma2(qa[i], kt[i], da0);
                da1 = ffma2(qa[i + 1], kt[i + 1], da1);
                db0 = ffma2(qb2[i], kt[i], db0);
                db1 = ffma2(qb2[i + 1], kt[i + 1], db1);
            }
            float2 ea0 = unpack2(da0), ea1 = unpack2(da1);
            float2 eb0 = unpack2(db0), eb1 = unpack2(db1);
            float pa = __expf((ea0.x + ea0.y) + (ea1.x + ea1.y));
            float pb = __expf((eb0.x + eb0.y) + (eb1.x + eb1.y));
            la += pa; lb += pb;
            u64 pa2 = pack2(pa, pa);
            u64 pb2 = pack2(pb, pb);
            u64 vt2[16];
            #pragma unroll
            for (int i = 0; i < 8; i++) lds2(&vs[j][i * 4], vt2[2 * i], vt2[2 * i + 1]);
            #pragma unroll
            for (int i = 0; i < 16; i++) {
                aa[i] = ffma2(pa2, vt2[i], aa[i]);
                ab[i] = ffma2(pb2, vt2[i], ab[i]);
            }
        }
        __syncthreads();
    }

    long ob = (long)b * CC + h * HD;
    if (va) {
        float inv = 1.f / la;
        #pragma unroll
        for (int i = 0; i < 16; i++) {
            float2 t = unpack2(aa[i]);
            out[(ob + 2 * i) * (long)Ssz + rowa] = t.x * inv;
            out[(ob + 2 * i + 1) * (long)Ssz + rowa] = t.y * inv;
        }
    }
    if (vb) {
        float inv = 1.f / lb;
        #pragma unroll
        for (int i = 0; i < 16; i++) {
            float2 t = unpack2(ab[i]);
            out[(ob + 2 * i) * (long)Ssz + rowb] = t.x * inv;
            out[(ob + 2 * i + 1) * (long)Ssz + rowb] = t.y * inv;
        }
    }
}

// ---------------- 4x4 average pool ----------------
__global__ void avgpool_kernel(const float* __restrict__ x, float* __restrict__ xc)
{
    int idx = blockIdx.x * blockDim.x + threadIdx.x;
    if (idx >= BB * CC * SG) return;
    int p = idx % SG;
    int c = (idx / SG) % CC;
    int b = idx / (SG * CC);
    int i = p / 12, j = p % 12;
    const float* xp = x + ((long)b * CC + c) * SL;
    float s = 0.f;
    #pragma unroll
    for (int dy = 0; dy < 4; dy++)
        #pragma unroll
        for (int dx = 0; dx < 4; dx++)
            s += xp[(i * 4 + dy) * 48 + j * 4 + dx];
    xc[idx] = s * (1.f / 16.f);
}

// ---------------- bilinear upsample into concat ch 256..511 ----------------
__global__ void upsample_kernel(const float* __restrict__ g, float* __restrict__ concat)
{
    int idx = blockIdx.x * blockDim.x + threadIdx.x;
    if (idx >= BB * CC * SL) return;
    int p = idx % SL;
    int c = (idx / SL) % CC;
    int b = idx / (SL * CC);
    int y = p / 48, x = p % 48;
    float fy = (y + 0.5f) * 0.25f - 0.5f;
    float fx = (x + 0.5f) * 0.25f - 0.5f;
    int y0 = (int)floorf(fy), x0 = (int)floorf(fx);
    float wy = fy - y0, wx = fx - x0;
    int ya = min(11, max(0, y0)), yb = min(11, max(0, y0 + 1));
    int xa = min(11, max(0, x0)), xb = min(11, max(0, x0 + 1));
    const float* gp = g + ((long)b * CC + c) * SG;
    float v00 = gp[ya * 12 + xa], v01 = gp[ya * 12 + xb];
    float v10 = gp[yb * 12 + xa], v11 = gp[yb * 12 + xb];
    float v = (1.f - wy) * ((1.f - wx) * v00 + wx * v01)
            +        wy  * ((1.f - wx) * v10 + wx * v11);
    concat[((long)b * 512 + 256 + c) * SL + p] = v;
}

// ---------------- launch ----------------
extern "C" void kernel_launch(void* const* d_in, const int* in_sizes, int n_in,
                              void* d_out, int out_size)
{
    const float* x        = (const float*)d_in[0];
    const float* w_qkv_l  = (const float*)d_in[1];
    const float* w_proj_l = (const float*)d_in[2];
    const float* b_proj_l = (const float*)d_in[3];
    const float* w_qkv_g  = (const float*)d_in[4];
    const float* w_proj_g = (const float*)d_in[5];
    const float* b_proj_g = (const float*)d_in[6];
    const float* w_f1     = (const float*)d_in[7];
    const float* b_f1     = (const float*)d_in[8];
    const float* w_f2     = (const float*)d_in[9];
    const float* b_f2     = (const float*)d_in[10];
    float* out = (float*)d_out;

    float *qkv, *attn, *concat, *hbuf, *xc, *qkvg, *qkvtg, *attng, *gg, *vsum;
    __nv_bfloat16* vt;
    u32 *wh, *wl, *kb, *qb;
    cudaGetSymbolAddress((void**)&qkv,    g_qkv);
    cudaGetSymbolAddress((void**)&attn,   g_attn);
    cudaGetSymbolAddress((void**)&concat, g_concat);
    cudaGetSymbolAddress((void**)&hbuf,   g_h);
    cudaGetSymbolAddress((void**)&xc,     g_xc);
    cudaGetSymbolAddress((void**)&qkvg,   g_qkvg);
    cudaGetSymbolAddress((void**)&qkvtg,  g_qkvtg);
    cudaGetSymbolAddress((void**)&attng,  g_attng);
    cudaGetSymbolAddress((void**)&gg,     g_g);
    cudaGetSymbolAddress((void**)&vt,     g_vt);
    cudaGetSymbolAddress((void**)&vsum,   g_vsum);
    cudaGetSymbolAddress((void**)&wh,     g_wh);
    cudaGetSymbolAddress((void**)&wl,     g_wl);
    cudaGetSymbolAddress((void**)&kb,     g_kb);
    cudaGetSymbolAddress((void**)&qb,     g_qb);

    static cudaStream_t s2 = nullptr;
    static cudaEvent_t evF = nullptr, evJ = nullptr;
    if (!s2) {
        cudaStreamCreateWithFlags(&s2, cudaStreamNonBlocking);
        cudaEventCreateWithFlags(&evF, cudaEventDisableTiming);
        cudaEventCreateWithFlags(&evJ, cudaEventDisableTiming);
    }

    dim3 blk(16, 16);

    cudaEventRecord(evF, 0);
    cudaStreamWaitEvent(s2, evF, 0);

    // ---- global branch (s2) ----
    avgpool_kernel<<<(BB * CC * SG + 255) / 256, 256, 0, s2>>>(x, xc);
    gemm_kernel<128><<<dim3((SG + 63) / 64, 768 / 128, BB), blk, 0, s2>>>(xc, w_qkv_g, nullptr, qkvg,
                                                                          256, SG, 256L * SG, 768L * SG, 0);
    tnorm_kernel<<<dim3((SG + 31) / 32, BB * 24), dim3(32, 32), 0, s2>>>(qkvg, qkvtg, SG, vt, vsum, kb, qb, 0);
    attn_kernel<<<dim3(BB * HEADS, (SG + 255) / 256), 128, 0, s2>>>(qkvtg, attng, SG);
    gemm_kernel<128><<<dim3((SG + 63) / 64, 256 / 128, BB), blk, 0, s2>>>(attng, w_proj_g, b_proj_g, gg,
                                                                          256, SG, 256L * SG, 256L * SG, 0);
    upsample_kernel<<<(BB * CC * SL + 255) / 256, 256, 0, s2>>>(gg, concat);
    cudaEventRecord(evJ, s2);

    // ---- local branch (stream 0) ----
    cudaMemsetAsync(vsum, 0, BB * HEADS * 32 * sizeof(float), 0);
    wsplit_all_kernel<<<(WTOT + 255) / 256, 256>>>(w_qkv_l, w_proj_l, w_f1, w_f2, wh, wl);
    gemm_tc_kernel<0><<<dim3(SL / 128, 768 / 128, BB), 256>>>(x, wh + WOFF_QKV, wl + WOFF_QKV,
                                                              nullptr, qkv, 256, SL, 256L * SL, 768L * SL);
    tnorm_kernel<<<dim3(SL / 32, BB * 24), dim3(32, 32)>>>(qkv, nullptr, SL, vt, vsum, kb, qb, 1);
    attn_tc_kernel<<<dim3(BB * HEADS, SL / 128), 128>>>(qb, kb, vt, vsum, attn);
    gemm_tc_kernel<0><<<dim3(SL / 128, 256 / 128, BB), 256>>>(attn, wh + WOFF_PROJ, wl + WOFF_PROJ,
                                                              b_proj_l, concat, 256, SL, 256L * SL, 512L * SL);

    // join: f1 needs both halves of concat
    cudaStreamWaitEvent(0, evJ, 0);

    gemm_tc_kernel<1><<<dim3(SL / 128, 256 / 128, BB), 256>>>(concat, wh + WOFF_F1, wl + WOFF_F1,
                                                              b_f1, hbuf, 512, SL, 512L * SL, 256L * SL);
    gemm_tc_kernel<0><<<dim3(SL / 128, 256 / 128, BB), 256>>>(hbuf, wh + WOFF_F2, wl + WOFF_F2,
                                                              b_f2, out, 256, SL, 256L * SL, 256L * SL);
}